// round 10
// baseline (speedup 1.0000x reference)
#include <cuda_runtime.h>
#include <cstdint>
#include <cstddef>

#define NB 4
#define NS 512
#define NH 8
#define NDH 64
#define NDM 512
#define NBH 32

// ---- scratch (device globals; no allocation) ----
__device__ float g_xc[2048 * 512];            // X, tf32-rounded
__device__ float g_wc[3 * 512 * 512];         // Wq|Wk|Wv, tf32-rounded
__device__ float g_wrc[64 * 64];              // Wr, tf32-rounded
__device__ float g_q [NBH * NS * NDH];        // tf32-rounded
__device__ float g_k [NBH * NS * NDH];        // tf32-rounded
__device__ float g_v [NBH * NDH * NS];        // transposed [bh][d][s], tf32-rounded
__device__ float g_qr[NBH * NS * NDH];        // tf32-rounded, pre-scaled by 0.125
__device__ float g_qb[NBH * NS];              // pre-scaled by 0.125
__device__ float g_s1[(size_t)NB * NS * NH * NS];  // qk scores [b][q][h][k], pre-scaled
__device__ float g_rs[(size_t)NB * NS * NH * NS];  // rel scores [b][q][h][k], pre-scaled
__device__ float g_p [(size_t)NB * NS * NH * NS];  // probs [b][q][h][k], tf32-rounded

__device__ __forceinline__ uint32_t f2tf(float x) {
    uint32_t r; asm("cvt.rna.tf32.f32 %0, %1;" : "=r"(r) : "f"(x)); return r;
}
__device__ __forceinline__ float f2tff(float x) { return __uint_as_float(f2tf(x)); }
__device__ __forceinline__ void mma8(float* d, const uint32_t* a, const uint32_t* b) {
    asm volatile(
        "mma.sync.aligned.m16n8k8.row.col.f32.tf32.tf32.f32 "
        "{%0,%1,%2,%3}, {%4,%5,%6,%7}, {%8,%9}, {%0,%1,%2,%3};"
        : "+f"(d[0]), "+f"(d[1]), "+f"(d[2]), "+f"(d[3])
        : "r"(a[0]), "r"(a[1]), "r"(a[2]), "r"(a[3]), "r"(b[0]), "r"(b[1]));
}
__device__ __forceinline__ void cpa16(const void* smem_dst, const void* gmem_src) {
    uint32_t s = (uint32_t)__cvta_generic_to_shared(smem_dst);
    asm volatile("cp.async.cg.shared.global [%0], [%1], 16;" :: "r"(s), "l"(gmem_src));
}
#define CP_COMMIT() asm volatile("cp.async.commit_group;")
#define CP_WAIT1()  asm volatile("cp.async.wait_group 1;")
#define CP_WAIT0()  asm volatile("cp.async.wait_group 0;")

// ======== K0: pre-round X / Wq / Wk / Wv / Wr to tf32 bit patterns =========
#define CVT_X4  262144
#define CVT_W4  196608
#define CVT_R4  1024
#define CVT_N   (CVT_X4 + CVT_W4 + CVT_R4)

__global__ void __launch_bounds__(256) k_cvt(const float* __restrict__ X,
                                             const float* __restrict__ W0,
                                             const float* __restrict__ W1,
                                             const float* __restrict__ W2,
                                             const float* __restrict__ Wr) {
    int i = blockIdx.x * 256 + threadIdx.x;
    if (i >= CVT_N) return;
    float4 v; float4* dst;
    if (i < CVT_X4) {
        v = ((const float4*)X)[i];
        dst = &((float4*)g_xc)[i];
    } else if (i < CVT_X4 + CVT_W4) {
        int j = i - CVT_X4, z = j >> 16, r = j & 65535;
        const float* Ws = (z == 0) ? W0 : (z == 1) ? W1 : W2;
        v = ((const float4*)Ws)[r];
        dst = &((float4*)g_wc)[j];
    } else {
        int j = i - CVT_X4 - CVT_W4;
        v = ((const float4*)Wr)[j];
        dst = &((float4*)g_wrc)[j];
    }
    v.x = f2tff(v.x); v.y = f2tff(v.y); v.z = f2tff(v.z); v.w = f2tff(v.w);
    *dst = v;
}

// ========= K1: q/k/v = X @ W^T (2048x512x512), 3-stage ring, single-sync;
//           z = zbase + blockIdx.z; z==0 also computes qr and qb ============
#define K1_SMEM (13824 * 4)

__global__ void __launch_bounds__(256) k_qkv(const float* __restrict__ br, int zbase) {
    extern __shared__ float dsm[];
    const int z = zbase + blockIdx.z;
    const float* __restrict__ X = g_xc;
    const float* __restrict__ W = g_wc + (size_t)z * 262144;
    const int tid = threadIdx.x, lane = tid & 31, w = tid >> 5;
    const int g = lane >> 2, t = lane & 3, wm = w >> 2, wn = w & 3;
    const int m0 = blockIdx.x * 64, n0 = blockIdx.y * 64;
    const int lr = tid >> 3, lc = (tid & 7) * 4;
    float acc[2][2][4] = {};

    auto issue = [&](int ki) {
        int st = ki % 3, kt = ki * 32;
        float* Xs = dsm + st * 2304;
        float* Ws = dsm + 6912 + st * 2304;
#pragma unroll
        for (int rr = 0; rr < 2; rr++) {
            int r = lr + rr * 32;
            cpa16(&Xs[r * 36 + lc], &X[(size_t)(m0 + r) * NDM + kt + lc]);
            cpa16(&Ws[r * 36 + lc], &W[(size_t)(n0 + r) * NDM + kt + lc]);
        }
    };
    issue(0); CP_COMMIT();
    issue(1); CP_COMMIT();
    for (int ki = 0; ki < 16; ki++) {
        if (ki < 15) CP_WAIT1(); else CP_WAIT0();
        __syncthreads();
        if (ki < 14) { issue(ki + 2); CP_COMMIT(); }
        int st = ki % 3;
        const float* Xf = dsm + st * 2304;
        const float* Wf = dsm + 6912 + st * 2304;
#pragma unroll
        for (int ks = 0; ks < 4; ks++) {
            uint32_t a[2][4], bb[2][2];
#pragma unroll
            for (int mi = 0; mi < 2; mi++) {
                int r = wm * 32 + mi * 16 + g;
                a[mi][0] = __float_as_uint(Xf[r*36 + ks*8 + t]);
                a[mi][1] = __float_as_uint(Xf[(r+8)*36 + ks*8 + t]);
                a[mi][2] = __float_as_uint(Xf[r*36 + ks*8 + t + 4]);
                a[mi][3] = __float_as_uint(Xf[(r+8)*36 + ks*8 + t + 4]);
            }
#pragma unroll
            for (int ni = 0; ni < 2; ni++) {
                int c = wn * 16 + ni * 8 + g;
                bb[ni][0] = __float_as_uint(Wf[c*36 + ks*8 + t]);
                bb[ni][1] = __float_as_uint(Wf[c*36 + ks*8 + t + 4]);
            }
#pragma unroll
            for (int mi = 0; mi < 2; mi++)
#pragma unroll
                for (int ni = 0; ni < 2; ni++) mma8(acc[mi][ni], a[mi], bb[ni]);
        }
    }
#pragma unroll
    for (int mi = 0; mi < 2; mi++)
#pragma unroll
        for (int ni = 0; ni < 2; ni++) {
            int m = m0 + wm*32 + mi*16 + g, n = n0 + wn*16 + ni*8 + 2*t;
            int b = m >> 9, s = m & 511, h = n >> 6, d = n & 63, bh = b*NH + h;
            if (z == 2) {
                g_v[(bh*NDH + d)  *NS + s]     = f2tff(acc[mi][ni][0]);
                g_v[(bh*NDH + d+1)*NS + s]     = f2tff(acc[mi][ni][1]);
                g_v[(bh*NDH + d)  *NS + s + 8] = f2tff(acc[mi][ni][2]);
                g_v[(bh*NDH + d+1)*NS + s + 8] = f2tff(acc[mi][ni][3]);
            } else {
                float* o = (z == 0) ? g_q : g_k;
                float* o1 = &o[((bh*NS + s)    *NDH) + d];
                float* o2 = &o[((bh*NS + s + 8)*NDH) + d];
                o1[0]=f2tff(acc[mi][ni][0]); o1[1]=f2tff(acc[mi][ni][1]);
                o2[0]=f2tff(acc[mi][ni][2]); o2[1]=f2tff(acc[mi][ni][3]);
            }
        }
    if (z != 0) return;

    // ---- fused qr/qb epilogue (this CTA holds q[m0..m0+63][head hB][0..63]) --
    float* Qs  = dsm;            // [64][68]
    float* WrT = dsm + 6912;     // [64 r][68 d]
    float* brs = dsm + 11264;
    const int hB = blockIdx.y;
    __syncthreads();
#pragma unroll
    for (int mi = 0; mi < 2; mi++)
#pragma unroll
        for (int ni = 0; ni < 2; ni++) {
            int ml = wm*32 + mi*16 + g, nl = wn*16 + ni*8 + 2*t;
            Qs[ml*68 + nl] = acc[mi][ni][0];     Qs[ml*68 + nl + 1] = acc[mi][ni][1];
            Qs[(ml+8)*68 + nl] = acc[mi][ni][2]; Qs[(ml+8)*68 + nl + 1] = acc[mi][ni][3];
        }
    for (int i = tid; i < 4096; i += 256) {
        int d = i >> 6, r = i & 63;
        WrT[r*68 + d] = g_wrc[i];
    }
    if (tid < 64) brs[tid] = br[tid];
    __syncthreads();

    float qacc[2][2][4] = {};
#pragma unroll
    for (int ks = 0; ks < 8; ks++) {
        uint32_t a[2][4], bb[2][2];
#pragma unroll
        for (int mi = 0; mi < 2; mi++) {
            int r = wm * 32 + mi * 16 + g;
            a[mi][0] = f2tf(Qs[r*68 + ks*8 + t]);     a[mi][1] = f2tf(Qs[(r+8)*68 + ks*8 + t]);
            a[mi][2] = f2tf(Qs[r*68 + ks*8 + t + 4]); a[mi][3] = f2tf(Qs[(r+8)*68 + ks*8 + t + 4]);
        }
#pragma unroll
        for (int ni = 0; ni < 2; ni++) {
            int c = wn * 16 + ni * 8 + g;
            bb[ni][0] = __float_as_uint(WrT[c*68 + ks*8 + t]);
            bb[ni][1] = __float_as_uint(WrT[c*68 + ks*8 + t + 4]);
        }
#pragma unroll
        for (int mi = 0; mi < 2; mi++)
#pragma unroll
            for (int ni = 0; ni < 2; ni++) mma8(qacc[mi][ni], a[mi], bb[ni]);
    }
#pragma unroll
    for (int mi = 0; mi < 2; mi++)
#pragma unroll
        for (int ni = 0; ni < 2; ni++) {
            int ml = wm*32 + mi*16 + g, col = wn*16 + ni*8 + 2*t;
            int m = m0 + ml, b = m >> 9, s = m & 511;
            float* o1 = &g_qr[(((size_t)(b*NH + hB)*NS + s)     ) * NDH + col];
            float* o2 = &g_qr[(((size_t)(b*NH + hB)*NS + (s+8)) ) * NDH + col];
            o1[0] = f2tff(qacc[mi][ni][0]) * 0.125f; o1[1] = f2tff(qacc[mi][ni][1]) * 0.125f;
            o2[0] = f2tff(qacc[mi][ni][2]) * 0.125f; o2[1] = f2tff(qacc[mi][ni][3]) * 0.125f;
        }
    {
        int row = tid >> 2, qg = tid & 3;
        float p = 0.f;
#pragma unroll
        for (int d = 0; d < 16; d++) p += Qs[row*68 + qg*16 + d] * brs[qg*16 + d];
        p += __shfl_xor_sync(0xffffffffu, p, 1);
        p += __shfl_xor_sync(0xffffffffu, p, 2);
        if (qg == 0) {
            int m = m0 + row, b = m >> 9, s = m & 511;
            g_qb[(b*NH + hB)*NS + s] = p * 0.125f;
        }
    }
}

// ======= K3: 0.125*q k^T per (b,h), scores -> [b][q][h][k]; no cvt ==========
__global__ void __launch_bounds__(256) k_qk() {
    const int bh = blockIdx.z, b = bh >> 3, h = bh & 7;
    const float* __restrict__ Q = &g_q[(size_t)bh * NS * NDH];
    const float* __restrict__ K = &g_k[(size_t)bh * NS * NDH];
    __shared__ float As[64 * 68], Bs[64 * 68];
    const int tid = threadIdx.x, lane = tid & 31, w = tid >> 5;
    const int g = lane >> 2, t = lane & 3, wm = w >> 2, wn = w & 3;
    const int m0 = blockIdx.x * 64, n0 = blockIdx.y * 64;
#pragma unroll
    for (int rr = 0; rr < 4; rr++) {
        int r = (tid >> 4) + rr * 16, c4 = (tid & 15) * 4;
        cpa16(&As[r * 68 + c4], &Q[(m0 + r) * NDH + c4]);
        cpa16(&Bs[r * 68 + c4], &K[(n0 + r) * NDH + c4]);
    }
    CP_COMMIT(); CP_WAIT0();
    __syncthreads();
    float acc[2][2][4] = {};
#pragma unroll
    for (int ks = 0; ks < 8; ks++) {
        uint32_t a[2][4], bb[2][2];
#pragma unroll
        for (int mi = 0; mi < 2; mi++) {
            int r = wm * 32 + mi * 16 + g;
            a[mi][0] = __float_as_uint(As[r*68 + ks*8 + t]);
            a[mi][1] = __float_as_uint(As[(r+8)*68 + ks*8 + t]);
            a[mi][2] = __float_as_uint(As[r*68 + ks*8 + t + 4]);
            a[mi][3] = __float_as_uint(As[(r+8)*68 + ks*8 + t + 4]);
        }
#pragma unroll
        for (int ni = 0; ni < 2; ni++) {
            int c = wn * 16 + ni * 8 + g;
            bb[ni][0] = __float_as_uint(Bs[c*68 + ks*8 + t]);
            bb[ni][1] = __float_as_uint(Bs[c*68 + ks*8 + t + 4]);
        }
#pragma unroll
        for (int mi = 0; mi < 2; mi++)
#pragma unroll
            for (int ni = 0; ni < 2; ni++) mma8(acc[mi][ni], a[mi], bb[ni]);
    }
#pragma unroll
    for (int mi = 0; mi < 2; mi++)
#pragma unroll
        for (int ni = 0; ni < 2; ni++) {
            int m = m0 + wm*32 + mi*16 + g, n = n0 + wn*16 + ni*8 + 2*t;
            float* o1 = &g_s1[((size_t)(b*NS + m)    *NH + h)*NS + n];
            float* o2 = &g_s1[((size_t)(b*NS + m + 8)*NH + h)*NS + n];
            o1[0] = acc[mi][ni][0] * 0.125f; o1[1] = acc[mi][ni][1] * 0.125f;
            o2[0] = acc[mi][ni][2] * 0.125f; o2[1] = acc[mi][ni][3] * 0.125f;
        }
}

// ===== K4a: per (b,q): rel mma + qb -> g_rs (NO scores/softmax dependency) ==
#define RELW   (128 * 68)
#define OFF_QR (2 * RELW)
#define OFF_QB (OFF_QR + 8 * 68)
#define K4_SMEM ((OFF_QB + 8) * 4)

__global__ void __launch_bounds__(256) k_rel(const float* __restrict__ REL) {
    extern __shared__ float sm[];
    float* relb = sm;
    uint32_t* qrs = (uint32_t*)(sm + OFF_QR);
    float* qbs = sm + OFF_QB;

    const int q = blockIdx.x, b = blockIdx.y;
    const int tid = threadIdx.x, lane = tid & 31, w = tid >> 5;
    const int g = lane >> 2, t = lane & 3;

    const float* relrow = REL + (size_t)(b*NS + q) * NS * NDH;

    auto issue_rel = [&](int ch) {
        const float* src = relrow + (size_t)ch * 128 * NDH;
        float* dst = relb + (ch & 1) * RELW;
        int c4 = (tid & 15) * 4, r0 = tid >> 4;
#pragma unroll
        for (int rr = 0; rr < 8; rr++) {
            int r = r0 + rr * 16;
            cpa16(&dst[r * 68 + c4], src + (size_t)r * NDH + c4);
        }
    };
    issue_rel(0); CP_COMMIT();
    issue_rel(1); CP_COMMIT();

    if (tid < 8) qbs[tid] = g_qb[(b*NH + tid)*NS + q];
    for (int i = tid; i < 512; i += 256) {
        int h = i >> 6, r = i & 63;
        qrs[h * 68 + r] = __float_as_uint(g_qr[(size_t)((b*NH + h)*NS + q) * NDH + r]);
    }
    __syncthreads();
    uint32_t bf[8][2];
#pragma unroll
    for (int ks = 0; ks < 8; ks++) {
        bf[ks][0] = qrs[g*68 + ks*8 + t];
        bf[ks][1] = qrs[g*68 + ks*8 + t + 4];
    }
    const float qb0 = qbs[2*t], qb1 = qbs[2*t + 1];

    float sc[16];
    for (int ch = 0; ch < 4; ch++) {
        if (ch < 3) CP_WAIT1(); else CP_WAIT0();
        __syncthreads();
        const float* buf = relb + (ch & 1) * RELW;
        float c[4] = {0,0,0,0};
        int r0 = w * 16 + g;
#pragma unroll
        for (int ks = 0; ks < 8; ks++) {
            uint32_t a[4];
            a[0] = f2tf(buf[r0*68 + ks*8 + t]);     a[1] = f2tf(buf[(r0+8)*68 + ks*8 + t]);
            a[2] = f2tf(buf[r0*68 + ks*8 + t + 4]); a[3] = f2tf(buf[(r0+8)*68 + ks*8 + t + 4]);
            mma8(c, a, bf[ks]);
        }
#pragma unroll
        for (int j = 0; j < 4; j++)
            sc[ch*4+j] = c[j] + ((j & 1) ? qb1 : qb0);
        __syncthreads();
        if (ch < 2) { issue_rel(ch + 2); CP_COMMIT(); }
    }
    // stage [h][k] into relb (free now), then contiguous float4 store
    float* pbuf = relb;
#pragma unroll
    for (int ch = 0; ch < 4; ch++) {
        int k0 = ch * 128 + w * 16;
#pragma unroll
        for (int j = 0; j < 4; j++) {
            int k = k0 + g + ((j >= 2) ? 8 : 0);
            int h = 2 * t + (j & 1);
            pbuf[h * NS + k] = sc[ch*4+j];
        }
    }
    __syncthreads();
    float* pout = &g_rs[(size_t)(b*NS + q) * NH * NS];
    for (int i = tid; i < 1024; i += 256)
        *(float4*)&pout[i * 4] = *(const float4*)&pbuf[i * 4];
}

// ===== K4b: softmax(s1 + rs + mask) -> probs; warp w = head w ===============
__global__ void __launch_bounds__(256) k_sm(const int* __restrict__ GRAPH) {
    const int q = blockIdx.x, b = blockIdx.y;
    const int lane = threadIdx.x & 31, h = threadIdx.x >> 5;
    const float4* s1r = (const float4*)&g_s1[((size_t)(b*NS + q)*NH + h)*NS];
    const float4* rsr = (const float4*)&g_rs[((size_t)(b*NS + q)*NH + h)*NS];
    const int4*   gr  = (const int4*)&GRAPH[(size_t)(b*NS + q) * NS];
    float4 v[4];
    float mx = -3e38f;
#pragma unroll
    for (int j = 0; j < 4; j++) {
        int k4 = lane + j * 32;
        float4 a = s1r[k4];
        float4 c = rsr[k4];
        int4 gi = gr[k4];
        a.x += c.x + (1.f - (float)gi.x) * -1e9f;
        a.y += c.y + (1.f - (float)gi.y) * -1e9f;
        a.z += c.z + (1.f - (float)gi.z) * -1e9f;
        a.w += c.w + (1.f - (float)gi.w) * -1e9f;
        v[j] = a;
        mx = fmaxf(mx, fmaxf(fmaxf(a.x, a.y), fmaxf(a.z, a.w)));
    }
#pragma unroll
    for (int o = 16; o; o >>= 1) mx = fmaxf(mx, __shfl_xor_sync(0xffffffffu, mx, o));
    float s = 0.f;
#pragma unroll
    for (int j = 0; j < 4; j++) {
        v[j].x = __expf(v[j].x - mx); v[j].y = __expf(v[j].y - mx);
        v[j].z = __expf(v[j].z - mx); v[j].w = __expf(v[j].w - mx);
        s += v[j].x + v[j].y + v[j].z + v[j].w;
    }
#pragma unroll
    for (int o = 16; o; o >>= 1) s += __shfl_xor_sync(0xffffffffu, s, o);
    float ri = 1.f / s;
    float4* pout = (float4*)&g_p[((size_t)(b*NS + q)*NH + h)*NS];
#pragma unroll
    for (int j = 0; j < 4; j++) {
        float4 o4;
        o4.x = f2tff(v[j].x * ri); o4.y = f2tff(v[j].y * ri);
        o4.z = f2tff(v[j].z * ri); o4.w = f2tff(v[j].w * ri);
        pout[lane + j * 32] = o4;
    }
}

// ========= K5: out = probs @ v per (b,h), BM=64, 2-stage single-sync, no cvt
__global__ void __launch_bounds__(256) k_pv(float* __restrict__ OUT) {
    const int bh = blockIdx.z, b = bh >> 3, h = bh & 7;
    const float* __restrict__ VT = &g_v[(size_t)bh * NDH * NS];
    __shared__ float As[2][64 * 36], Bs[2][64 * 36];
    const int tid = threadIdx.x, lane = tid & 31, w = tid >> 5;
    const int g = lane >> 2, t = lane & 3, wm = w >> 2, wn = w & 3;
    const int m0 = blockIdx.x * 64;
    const int lr = tid >> 3, lc = (tid & 7) * 4;
    float acc[2][2][4] = {};

    auto issue = [&](int ki) {
        int bi = ki & 1, kt = ki * 32;
#pragma unroll
        for (int rr = 0; rr < 2; rr++) {
            int r = lr + rr * 32;
            cpa16(&As[bi][r * 36 + lc], &g_p[((size_t)(b*NS + m0 + r)*NH + h)*NS + kt + lc]);
            cpa16(&Bs[bi][r * 36 + lc], &VT[(size_t)r * NS + kt + lc]);
        }
    };
    issue(0); CP_COMMIT();
    for (int ki = 0; ki < 16; ki++) {
        CP_WAIT0();
        __syncthreads();
        if (ki < 15) { issue(ki + 1); CP_COMMIT(); }
        const float* Af = As[ki & 1];
        const float* Bf = Bs[ki & 1];
#pragma unroll
        for (int ks = 0; ks < 4; ks++) {
            uint32_t a[2][4], bb[2][2];
#pragma unroll
            for (int mi = 0; mi < 2; mi++) {
                int r = wm * 32 + mi * 16 + g;
                a[mi][0] = __float_as_uint(Af[r*36 + ks*8 + t]);
                a[mi][1] = __float_as_uint(Af[(r+8)*36 + ks*8 + t]);
                a[mi][2] = __float_as_uint(Af[r*36 + ks*8 + t + 4]);
                a[mi][3] = __float_as_uint(Af[(r+8)*36 + ks*8 + t + 4]);
            }
#pragma unroll
            for (int ni = 0; ni < 2; ni++) {
                int c = wn * 16 + ni * 8 + g;
                bb[ni][0] = __float_as_uint(Bf[c*36 + ks*8 + t]);
                bb[ni][1] = __float_as_uint(Bf[c*36 + ks*8 + t + 4]);
            }
#pragma unroll
            for (int mi = 0; mi < 2; mi++)
#pragma unroll
                for (int ni = 0; ni < 2; ni++) mma8(acc[mi][ni], a[mi], bb[ni]);
        }
    }
#pragma unroll
    for (int mi = 0; mi < 2; mi++)
#pragma unroll
        for (int ni = 0; ni < 2; ni++) {
            int m = m0 + wm*32 + mi*16 + g, n = wn*16 + ni*8 + 2*t;
            float* o1 = &OUT[(size_t)(b*NS + m)    *NDM + h*NDH + n];
            float* o2 = &OUT[(size_t)(b*NS + m + 8)*NDM + h*NDH + n];
            o1[0]=acc[mi][ni][0]; o1[1]=acc[mi][ni][1];
            o2[0]=acc[mi][ni][2]; o2[1]=acc[mi][ni][3];
        }
}

extern "C" void kernel_launch(void* const* d_in, const int* in_sizes, int n_in,
                              void* d_out, int out_size) {
    const float* X     = (const float*)d_in[0];
    const int*   GRAPH = (const int*)  d_in[1];
    const float* REL   = (const float*)d_in[2];
    const float* Wq    = (const float*)d_in[3];
    const float* Wk    = (const float*)d_in[4];
    const float* Wv    = (const float*)d_in[5];
    const float* Wr    = (const float*)d_in[6];
    const float* br    = (const float*)d_in[7];
    float* OUT = (float*)d_out;

    static cudaStream_t s2 = nullptr;
    static cudaEvent_t e0 = nullptr, e1 = nullptr;
    if (!s2) {
        cudaFuncSetAttribute(k_qkv, cudaFuncAttributeMaxDynamicSharedMemorySize, K1_SMEM);
        cudaFuncSetAttribute(k_rel, cudaFuncAttributeMaxDynamicSharedMemorySize, K4_SMEM);
        cudaStreamCreateWithFlags(&s2, cudaStreamNonBlocking);
        cudaEventCreateWithFlags(&e0, cudaEventDisableTiming);
        cudaEventCreateWithFlags(&e1, cudaEventDisableTiming);
    }

    k_cvt  <<<(CVT_N + 255) / 256, 256>>>(X, Wq, Wk, Wv, Wr);
    k_qkv  <<<dim3(32, 8, 1), 256, K1_SMEM>>>(br, 0);   // q + qr + qb

    cudaEventRecord(e0, 0);
    cudaStreamWaitEvent(s2, e0, 0);
    k_rel  <<<dim3(512, 4), 256, K4_SMEM, s2>>>(REL);    // overlapped rel stream
    cudaEventRecord(e1, s2);

    k_qkv  <<<dim3(32, 8, 2), 256, K1_SMEM>>>(br, 1);   // k + v
    k_qk   <<<dim3(8, 8, 32), 256>>>();

    cudaStreamWaitEvent(0, e1, 0);
    k_sm   <<<dim3(512, 4), 256>>>(GRAPH);
    k_pv   <<<dim3(8, 1, 32), 256>>>(OUT);
}

// round 11
// speedup vs baseline: 1.0838x; 1.0838x over previous
#include <cuda_runtime.h>
#include <cstdint>
#include <cstddef>

#define NB 4
#define NS 512
#define NH 8
#define NDH 64
#define NDM 512
#define NBH 32

// ---- scratch (device globals; no allocation) ----
__device__ float g_q [NBH * NS * NDH];        // tf32-rounded
__device__ float g_k [NBH * NS * NDH];        // tf32-rounded
__device__ float g_v [NBH * NDH * NS];        // transposed [bh][d][s], tf32-rounded
__device__ float g_qr[NBH * NS * NDH];        // tf32-rounded, pre-scaled by 0.125
__device__ float g_qb[NBH * NS];              // pre-scaled by 0.125
__device__ float g_s1[(size_t)NB * NS * NH * NS];  // scores [b][q][h][k], pre-scaled
__device__ float g_p [(size_t)NB * NS * NH * NS];  // probs  [b][q][h][k], tf32-rounded

__device__ __forceinline__ uint32_t f2tf(float x) {
    uint32_t r; asm("cvt.rna.tf32.f32 %0, %1;" : "=r"(r) : "f"(x)); return r;
}
__device__ __forceinline__ float f2tff(float x) { return __uint_as_float(f2tf(x)); }
__device__ __forceinline__ void mma8(float* d, const uint32_t* a, const uint32_t* b) {
    asm volatile(
        "mma.sync.aligned.m16n8k8.row.col.f32.tf32.tf32.f32 "
        "{%0,%1,%2,%3}, {%4,%5,%6,%7}, {%8,%9}, {%0,%1,%2,%3};"
        : "+f"(d[0]), "+f"(d[1]), "+f"(d[2]), "+f"(d[3])
        : "r"(a[0]), "r"(a[1]), "r"(a[2]), "r"(a[3]), "r"(b[0]), "r"(b[1]));
}
__device__ __forceinline__ void cpa16(const void* smem_dst, const void* gmem_src) {
    uint32_t s = (uint32_t)__cvta_generic_to_shared(smem_dst);
    asm volatile("cp.async.cg.shared.global [%0], [%1], 16;" :: "r"(s), "l"(gmem_src));
}
#define CP_COMMIT() asm volatile("cp.async.commit_group;")
#define CP_WAIT1()  asm volatile("cp.async.wait_group 1;")
#define CP_WAIT0()  asm volatile("cp.async.wait_group 0;")

// ========= K1: q/k/v = X @ W^T (2048x512x512), 3-stage ring, single-sync;
//           z==0 additionally computes qr = 0.125*q@Wr and qb = 0.125*q.br;
//           all outputs stored tf32-pre-rounded ============================
#define K1_SMEM (13824 * 4)

__global__ void __launch_bounds__(256) k_qkv(const float* __restrict__ X,
                                             const float* __restrict__ Wq,
                                             const float* __restrict__ Wk,
                                             const float* __restrict__ Wv,
                                             const float* __restrict__ Wr,
                                             const float* __restrict__ br) {
    extern __shared__ float dsm[];
    const int z = blockIdx.z;
    const float* __restrict__ W = (z == 0) ? Wq : (z == 1) ? Wk : Wv;
    const int tid = threadIdx.x, lane = tid & 31, w = tid >> 5;
    const int g = lane >> 2, t = lane & 3, wm = w >> 2, wn = w & 3;
    const int m0 = blockIdx.x * 64, n0 = blockIdx.y * 64;
    const int lr = tid >> 3, lc = (tid & 7) * 4;
    float acc[2][2][4] = {};

    auto issue = [&](int ki) {
        int st = ki % 3, kt = ki * 32;
        float* Xs = dsm + st * 2304;
        float* Ws = dsm + 6912 + st * 2304;
#pragma unroll
        for (int rr = 0; rr < 2; rr++) {
            int r = lr + rr * 32;
            cpa16(&Xs[r * 36 + lc], &X[(size_t)(m0 + r) * NDM + kt + lc]);
            cpa16(&Ws[r * 36 + lc], &W[(size_t)(n0 + r) * NDM + kt + lc]);
        }
    };
    issue(0); CP_COMMIT();
    issue(1); CP_COMMIT();
    for (int ki = 0; ki < 16; ki++) {
        if (ki < 15) CP_WAIT1(); else CP_WAIT0();
        __syncthreads();
        if (ki < 14) { issue(ki + 2); CP_COMMIT(); }
        int st = ki % 3;
        const float* Xf = dsm + st * 2304;
        const float* Wf = dsm + 6912 + st * 2304;
#pragma unroll
        for (int ks = 0; ks < 4; ks++) {
            uint32_t a[2][4], bb[2][2];
#pragma unroll
            for (int mi = 0; mi < 2; mi++) {
                int r = wm * 32 + mi * 16 + g;
                a[mi][0] = f2tf(Xf[r*36 + ks*8 + t]);     a[mi][1] = f2tf(Xf[(r+8)*36 + ks*8 + t]);
                a[mi][2] = f2tf(Xf[r*36 + ks*8 + t + 4]); a[mi][3] = f2tf(Xf[(r+8)*36 + ks*8 + t + 4]);
            }
#pragma unroll
            for (int ni = 0; ni < 2; ni++) {
                int c = wn * 16 + ni * 8 + g;
                bb[ni][0] = f2tf(Wf[c*36 + ks*8 + t]); bb[ni][1] = f2tf(Wf[c*36 + ks*8 + t + 4]);
            }
#pragma unroll
            for (int mi = 0; mi < 2; mi++)
#pragma unroll
                for (int ni = 0; ni < 2; ni++) mma8(acc[mi][ni], a[mi], bb[ni]);
        }
    }
    // global store of q/k/v, tf32-pre-rounded so consumers skip cvt
#pragma unroll
    for (int mi = 0; mi < 2; mi++)
#pragma unroll
        for (int ni = 0; ni < 2; ni++) {
            int m = m0 + wm*32 + mi*16 + g, n = n0 + wn*16 + ni*8 + 2*t;
            int b = m >> 9, s = m & 511, h = n >> 6, d = n & 63, bh = b*NH + h;
            if (z == 2) {
                g_v[(bh*NDH + d)  *NS + s]     = f2tff(acc[mi][ni][0]);
                g_v[(bh*NDH + d+1)*NS + s]     = f2tff(acc[mi][ni][1]);
                g_v[(bh*NDH + d)  *NS + s + 8] = f2tff(acc[mi][ni][2]);
                g_v[(bh*NDH + d+1)*NS + s + 8] = f2tff(acc[mi][ni][3]);
            } else {
                float* o = (z == 0) ? g_q : g_k;
                float* o1 = &o[((bh*NS + s)    *NDH) + d];
                float* o2 = &o[((bh*NS + s + 8)*NDH) + d];
                o1[0]=f2tff(acc[mi][ni][0]); o1[1]=f2tff(acc[mi][ni][1]);
                o2[0]=f2tff(acc[mi][ni][2]); o2[1]=f2tff(acc[mi][ni][3]);
            }
        }
    if (z != 0) return;

    // ---- fused qr/qb epilogue (this CTA holds q[m0..m0+63][head hB][0..63]) --
    float* Qs  = dsm;            // [64][68]
    float* WrT = dsm + 6912;     // [64 r][68 d]: WrT[r][d] = Wr[d][r]
    float* brs = dsm + 11264;
    const int hB = blockIdx.y;
    __syncthreads();   // everyone done reading stage buffers
#pragma unroll
    for (int mi = 0; mi < 2; mi++)
#pragma unroll
        for (int ni = 0; ni < 2; ni++) {
            int ml = wm*32 + mi*16 + g, nl = wn*16 + ni*8 + 2*t;
            Qs[ml*68 + nl] = acc[mi][ni][0];     Qs[ml*68 + nl + 1] = acc[mi][ni][1];
            Qs[(ml+8)*68 + nl] = acc[mi][ni][2]; Qs[(ml+8)*68 + nl + 1] = acc[mi][ni][3];
        }
    for (int i = tid; i < 4096; i += 256) {
        int d = i >> 6, r = i & 63;
        WrT[r*68 + d] = Wr[i];     // coalesced read
    }
    if (tid < 64) brs[tid] = br[tid];
    __syncthreads();

    float qacc[2][2][4] = {};
#pragma unroll
    for (int ks = 0; ks < 8; ks++) {
        uint32_t a[2][4], bb[2][2];
#pragma unroll
        for (int mi = 0; mi < 2; mi++) {
            int r = wm * 32 + mi * 16 + g;
            a[mi][0] = f2tf(Qs[r*68 + ks*8 + t]);     a[mi][1] = f2tf(Qs[(r+8)*68 + ks*8 + t]);
            a[mi][2] = f2tf(Qs[r*68 + ks*8 + t + 4]); a[mi][3] = f2tf(Qs[(r+8)*68 + ks*8 + t + 4]);
        }
#pragma unroll
        for (int ni = 0; ni < 2; ni++) {
            int c = wn * 16 + ni * 8 + g;
            bb[ni][0] = f2tf(WrT[c*68 + ks*8 + t]); bb[ni][1] = f2tf(WrT[c*68 + ks*8 + t + 4]);
        }
#pragma unroll
        for (int mi = 0; mi < 2; mi++)
#pragma unroll
            for (int ni = 0; ni < 2; ni++) mma8(qacc[mi][ni], a[mi], bb[ni]);
    }
#pragma unroll
    for (int mi = 0; mi < 2; mi++)
#pragma unroll
        for (int ni = 0; ni < 2; ni++) {
            int ml = wm*32 + mi*16 + g, col = wn*16 + ni*8 + 2*t;
            int m = m0 + ml, b = m >> 9, s = m & 511;
            float* o1 = &g_qr[(((size_t)(b*NH + hB)*NS + s)     ) * NDH + col];
            float* o2 = &g_qr[(((size_t)(b*NH + hB)*NS + (s+8)) ) * NDH + col];
            o1[0] = f2tff(qacc[mi][ni][0]) * 0.125f; o1[1] = f2tff(qacc[mi][ni][1]) * 0.125f;
            o2[0] = f2tff(qacc[mi][ni][2]) * 0.125f; o2[1] = f2tff(qacc[mi][ni][3]) * 0.125f;
        }
    // qb: 4 threads per row
    {
        int row = tid >> 2, qg = tid & 3;
        float p = 0.f;
#pragma unroll
        for (int d = 0; d < 16; d++) p += Qs[row*68 + qg*16 + d] * brs[qg*16 + d];
        p += __shfl_xor_sync(0xffffffffu, p, 1);
        p += __shfl_xor_sync(0xffffffffu, p, 2);
        if (qg == 0) {
            int m = m0 + row, b = m >> 9, s = m & 511;
            g_qb[(b*NH + hB)*NS + s] = p * 0.125f;
        }
    }
}

// ======= K3: 0.125*q k^T per (b,h), scores -> [b][q][h][k]; cvt-free ========
__global__ void __launch_bounds__(256) k_qk() {
    const int bh = blockIdx.z, b = bh >> 3, h = bh & 7;
    const float* __restrict__ Q = &g_q[(size_t)bh * NS * NDH];
    const float* __restrict__ K = &g_k[(size_t)bh * NS * NDH];
    __shared__ float As[64 * 68], Bs[64 * 68];
    const int tid = threadIdx.x, lane = tid & 31, w = tid >> 5;
    const int g = lane >> 2, t = lane & 3, wm = w >> 2, wn = w & 3;
    const int m0 = blockIdx.x * 64, n0 = blockIdx.y * 64;
#pragma unroll
    for (int rr = 0; rr < 4; rr++) {
        int r = (tid >> 4) + rr * 16, c4 = (tid & 15) * 4;
        cpa16(&As[r * 68 + c4], &Q[(m0 + r) * NDH + c4]);
        cpa16(&Bs[r * 68 + c4], &K[(n0 + r) * NDH + c4]);
    }
    CP_COMMIT(); CP_WAIT0();
    __syncthreads();
    float acc[2][2][4] = {};
#pragma unroll
    for (int ks = 0; ks < 8; ks++) {
        uint32_t a[2][4], bb[2][2];
#pragma unroll
        for (int mi = 0; mi < 2; mi++) {
            int r = wm * 32 + mi * 16 + g;
            a[mi][0] = __float_as_uint(As[r*68 + ks*8 + t]);
            a[mi][1] = __float_as_uint(As[(r+8)*68 + ks*8 + t]);
            a[mi][2] = __float_as_uint(As[r*68 + ks*8 + t + 4]);
            a[mi][3] = __float_as_uint(As[(r+8)*68 + ks*8 + t + 4]);
        }
#pragma unroll
        for (int ni = 0; ni < 2; ni++) {
            int c = wn * 16 + ni * 8 + g;
            bb[ni][0] = __float_as_uint(Bs[c*68 + ks*8 + t]);
            bb[ni][1] = __float_as_uint(Bs[c*68 + ks*8 + t + 4]);
        }
#pragma unroll
        for (int mi = 0; mi < 2; mi++)
#pragma unroll
            for (int ni = 0; ni < 2; ni++) mma8(acc[mi][ni], a[mi], bb[ni]);
    }
#pragma unroll
    for (int mi = 0; mi < 2; mi++)
#pragma unroll
        for (int ni = 0; ni < 2; ni++) {
            int m = m0 + wm*32 + mi*16 + g, n = n0 + wn*16 + ni*8 + 2*t;
            float* o1 = &g_s1[((size_t)(b*NS + m)    *NH + h)*NS + n];
            float* o2 = &g_s1[((size_t)(b*NS + m + 8)*NH + h)*NS + n];
            o1[0] = acc[mi][ni][0] * 0.125f; o1[1] = acc[mi][ni][1] * 0.125f;
            o2[0] = acc[mi][ni][2] * 0.125f; o2[1] = acc[mi][ni][3] * 0.125f;
        }
}

// ===== K4: per (b,q): rel mma + scores(reg) + mask + softmax ================
// dyn smem floats: relb[2][128*68] | qrs[8*68] | qbs[8] | red[128]
#define RELW   (128 * 68)
#define OFF_QR (2 * RELW)
#define OFF_QB (OFF_QR + 8 * 68)
#define OFF_RED (OFF_QB + 8)
#define K4_SMEM ((OFF_RED + 128) * 4)   // 72,992 bytes -> 3 CTAs/SM

__global__ void __launch_bounds__(256) k_relsm(const float* __restrict__ REL,
                                               const int* __restrict__ GRAPH) {
    extern __shared__ float sm[];
    float* relb = sm;
    uint32_t* qrs = (uint32_t*)(sm + OFF_QR);
    float* qbs = sm + OFF_QB;
    float* red = sm + OFF_RED;   // [2][8 warps][8 h]

    const int q = blockIdx.x, b = blockIdx.y;
    const int tid = threadIdx.x, lane = tid & 31, w = tid >> 5;
    const int g = lane >> 2, t = lane & 3;

    const float* relrow = REL + (size_t)(b*NS + q) * NS * NDH;
    const float* scrow  = &g_s1[(size_t)(b*NS + q) * NH * NS];
    const int*   grow   = &GRAPH[(size_t)(b*NS + q) * NS];

    auto issue_rel = [&](int ch) {
        const float* src = relrow + (size_t)ch * 128 * NDH;
        float* dst = relb + (ch & 1) * RELW;
        int c4 = (tid & 15) * 4, r0 = tid >> 4;
#pragma unroll
        for (int rr = 0; rr < 8; rr++) {
            int r = r0 + rr * 16;
            cpa16(&dst[r * 68 + c4], src + (size_t)r * NDH + c4);
        }
    };
    issue_rel(0); CP_COMMIT();
    issue_rel(1); CP_COMMIT();

    // scores + graph -> registers (masked at load)
    float sc[16];
#pragma unroll
    for (int ch = 0; ch < 4; ch++) {
        int k0 = ch * 128 + w * 16;
#pragma unroll
        for (int j = 0; j < 4; j++) {
            int k = k0 + g + ((j >= 2) ? 8 : 0);
            int h = 2 * t + (j & 1);
            sc[ch*4+j] = scrow[(size_t)h*NS + k] + (1.f - (float)grow[k]) * -1e9f;
        }
    }
    if (tid < 8) qbs[tid] = g_qb[(b*NH + tid)*NS + q];
    for (int i = tid; i < 512; i += 256) {
        int h = i >> 6, r = i & 63;
        qrs[h * 68 + r] = __float_as_uint(g_qr[(size_t)((b*NH + h)*NS + q) * NDH + r]);
    }
    __syncthreads();
    uint32_t bf[8][2];
#pragma unroll
    for (int ks = 0; ks < 8; ks++) {
        bf[ks][0] = qrs[g*68 + ks*8 + t];
        bf[ks][1] = qrs[g*68 + ks*8 + t + 4];
    }
    const float qb0 = qbs[2*t], qb1 = qbs[2*t + 1];

    for (int ch = 0; ch < 4; ch++) {
        if (ch < 3) CP_WAIT1(); else CP_WAIT0();
        __syncthreads();
        const float* buf = relb + (ch & 1) * RELW;
        float c[4] = {0,0,0,0};
        int r0 = w * 16 + g;
#pragma unroll
        for (int ks = 0; ks < 8; ks++) {
            uint32_t a[4];
            a[0] = f2tf(buf[r0*68 + ks*8 + t]);     a[1] = f2tf(buf[(r0+8)*68 + ks*8 + t]);
            a[2] = f2tf(buf[r0*68 + ks*8 + t + 4]); a[3] = f2tf(buf[(r0+8)*68 + ks*8 + t + 4]);
            mma8(c, a, bf[ks]);
        }
#pragma unroll
        for (int j = 0; j < 4; j++)
            sc[ch*4+j] += c[j] + ((j & 1) ? qb1 : qb0);
        __syncthreads();
        if (ch < 2) { issue_rel(ch + 2); CP_COMMIT(); }
    }
    // softmax: even sc index -> h=2t, odd -> h=2t+1
    float mx0 = -3e38f, mx1 = -3e38f;
#pragma unroll
    for (int i = 0; i < 16; i++) { if (i & 1) mx1 = fmaxf(mx1, sc[i]); else mx0 = fmaxf(mx0, sc[i]); }
#pragma unroll
    for (int o = 4; o < 32; o <<= 1) {
        mx0 = fmaxf(mx0, __shfl_xor_sync(0xffffffffu, mx0, o));
        mx1 = fmaxf(mx1, __shfl_xor_sync(0xffffffffu, mx1, o));
    }
    if (g == 0) { red[w*8 + 2*t] = mx0; red[w*8 + 2*t+1] = mx1; }
    __syncthreads();
    float fm0 = -3e38f, fm1 = -3e38f;
#pragma unroll
    for (int ww = 0; ww < 8; ww++) {
        fm0 = fmaxf(fm0, red[ww*8 + 2*t]); fm1 = fmaxf(fm1, red[ww*8 + 2*t+1]);
    }
    float s0 = 0.f, s1 = 0.f;
#pragma unroll
    for (int i = 0; i < 16; i++) {
        float e = __expf(sc[i] - ((i & 1) ? fm1 : fm0));
        sc[i] = e;
        if (i & 1) s1 += e; else s0 += e;
    }
#pragma unroll
    for (int o = 4; o < 32; o <<= 1) {
        s0 += __shfl_xor_sync(0xffffffffu, s0, o);
        s1 += __shfl_xor_sync(0xffffffffu, s1, o);
    }
    if (g == 0) { red[64 + w*8 + 2*t] = s0; red[64 + w*8 + 2*t+1] = s1; }
    __syncthreads();
    float ts0 = 0.f, ts1 = 0.f;
#pragma unroll
    for (int ww = 0; ww < 8; ww++) { ts0 += red[64 + ww*8 + 2*t]; ts1 += red[64 + ww*8 + 2*t+1]; }
    float r0i = 1.f / ts0, r1i = 1.f / ts1;

    // stage probs [h][k] into relb (tf32-rounded so k_pv skips cvt)
    float* pbuf = relb;
    __syncthreads();
#pragma unroll
    for (int ch = 0; ch < 4; ch++) {
        int k0 = ch * 128 + w * 16;
#pragma unroll
        for (int j = 0; j < 4; j++) {
            int k = k0 + g + ((j >= 2) ? 8 : 0);
            int h = 2 * t + (j & 1);
            pbuf[h * NS + k] = f2tff(sc[ch*4+j] * ((j & 1) ? r1i : r0i));
        }
    }
    __syncthreads();
    float* pout = &g_p[(size_t)(b*NS + q) * NH * NS];
    for (int i = tid; i < 1024; i += 256)
        *(float4*)&pout[i * 4] = *(const float4*)&pbuf[i * 4];
}

// ========= K5: out = probs @ v per (b,h), BM=64, 2-stage single-sync, cvt-free
__global__ void __launch_bounds__(256) k_pv(float* __restrict__ OUT) {
    const int bh = blockIdx.z, b = bh >> 3, h = bh & 7;
    const float* __restrict__ VT = &g_v[(size_t)bh * NDH * NS];
    __shared__ float As[2][64 * 36], Bs[2][64 * 36];
    const int tid = threadIdx.x, lane = tid & 31, w = tid >> 5;
    const int g = lane >> 2, t = lane & 3, wm = w >> 2, wn = w & 3;
    const int m0 = blockIdx.x * 64;
    const int lr = tid >> 3, lc = (tid & 7) * 4;
    float acc[2][2][4] = {};

    auto issue = [&](int ki) {
        int bi = ki & 1, kt = ki * 32;
#pragma unroll
        for (int rr = 0; rr < 2; rr++) {
            int r = lr + rr * 32;
            cpa16(&As[bi][r * 36 + lc], &g_p[((size_t)(b*NS + m0 + r)*NH + h)*NS + kt + lc]);
            cpa16(&Bs[bi][r * 36 + lc], &VT[(size_t)r * NS + kt + lc]);
        }
    };
    issue(0); CP_COMMIT();
    for (int ki = 0; ki < 16; ki++) {
        CP_WAIT0();
        __syncthreads();
        if (ki < 15) { issue(ki + 1); CP_COMMIT(); }
        const float* Af = As[ki & 1];
        const float* Bf = Bs[ki & 1];
#pragma unroll
        for (int ks = 0; ks < 4; ks++) {
            uint32_t a[2][4], bb[2][2];
#pragma unroll
            for (int mi = 0; mi < 2; mi++) {
                int r = wm * 32 + mi * 16 + g;
                a[mi][0] = __float_as_uint(Af[r*36 + ks*8 + t]);
                a[mi][1] = __float_as_uint(Af[(r+8)*36 + ks*8 + t]);
                a[mi][2] = __float_as_uint(Af[r*36 + ks*8 + t + 4]);
                a[mi][3] = __float_as_uint(Af[(r+8)*36 + ks*8 + t + 4]);
            }
#pragma unroll
            for (int ni = 0; ni < 2; ni++) {
                int c = wn * 16 + ni * 8 + g;
                bb[ni][0] = __float_as_uint(Bf[c*36 + ks*8 + t]);
                bb[ni][1] = __float_as_uint(Bf[c*36 + ks*8 + t + 4]);
            }
#pragma unroll
            for (int mi = 0; mi < 2; mi++)
#pragma unroll
                for (int ni = 0; ni < 2; ni++) mma8(acc[mi][ni], a[mi], bb[ni]);
        }
    }
#pragma unroll
    for (int mi = 0; mi < 2; mi++)
#pragma unroll
        for (int ni = 0; ni < 2; ni++) {
            int m = m0 + wm*32 + mi*16 + g, n = wn*16 + ni*8 + 2*t;
            float* o1 = &OUT[(size_t)(b*NS + m)    *NDM + h*NDH + n];
            float* o2 = &OUT[(size_t)(b*NS + m + 8)*NDM + h*NDH + n];
            o1[0]=acc[mi][ni][0]; o1[1]=acc[mi][ni][1];
            o2[0]=acc[mi][ni][2]; o2[1]=acc[mi][ni][3];
        }
}

extern "C" void kernel_launch(void* const* d_in, const int* in_sizes, int n_in,
                              void* d_out, int out_size) {
    const float* X     = (const float*)d_in[0];
    const int*   GRAPH = (const int*)  d_in[1];
    const float* REL   = (const float*)d_in[2];
    const float* Wq    = (const float*)d_in[3];
    const float* Wk    = (const float*)d_in[4];
    const float* Wv    = (const float*)d_in[5];
    const float* Wr    = (const float*)d_in[6];
    const float* br    = (const float*)d_in[7];
    float* OUT = (float*)d_out;

    static bool attr_set = false;
    if (!attr_set) {
        cudaFuncSetAttribute(k_qkv,   cudaFuncAttributeMaxDynamicSharedMemorySize, K1_SMEM);
        cudaFuncSetAttribute(k_relsm, cudaFuncAttributeMaxDynamicSharedMemorySize, K4_SMEM);
        attr_set = true;
    }

    k_qkv  <<<dim3(32, 8, 3), 256, K1_SMEM>>>(X, Wq, Wk, Wv, Wr, br);
    k_qk   <<<dim3(8, 8, 32), 256>>>();
    k_relsm<<<dim3(512, 4), 256, K4_SMEM>>>(REL, GRAPH);
    k_pv   <<<dim3(8, 1, 32), 256>>>(OUT);
}

// round 12
// speedup vs baseline: 1.0963x; 1.0115x over previous
#include <cuda_runtime.h>
#include <cstdint>
#include <cstddef>

#define NB 4
#define NS 512
#define NH 8
#define NDH 64
#define NDM 512
#define NBH 32

// ---- scratch (device globals; no allocation) ----
__device__ float g_q [NBH * NS * NDH];        // tf32-rounded
__device__ float g_k [NBH * NS * NDH];        // tf32-rounded
__device__ float g_v [NBH * NDH * NS];        // transposed [bh][d][s], tf32-rounded
__device__ float g_qr[NBH * NS * NDH];        // tf32-rounded, pre-scaled by 0.125
__device__ float g_qb[NBH * NS];              // pre-scaled by 0.125
__device__ float g_s1[(size_t)NB * NS * NH * NS];  // scores [b][q][h][k], pre-scaled
__device__ float g_p [(size_t)NB * NS * NH * NS];  // probs  [b][q][h][k], tf32-rounded

__device__ __forceinline__ uint32_t f2tf(float x) {
    uint32_t r; asm("cvt.rna.tf32.f32 %0, %1;" : "=r"(r) : "f"(x)); return r;
}
__device__ __forceinline__ float f2tff(float x) { return __uint_as_float(f2tf(x)); }
__device__ __forceinline__ void mma8(float* d, const uint32_t* a, const uint32_t* b) {
    asm volatile(
        "mma.sync.aligned.m16n8k8.row.col.f32.tf32.tf32.f32 "
        "{%0,%1,%2,%3}, {%4,%5,%6,%7}, {%8,%9}, {%0,%1,%2,%3};"
        : "+f"(d[0]), "+f"(d[1]), "+f"(d[2]), "+f"(d[3])
        : "r"(a[0]), "r"(a[1]), "r"(a[2]), "r"(a[3]), "r"(b[0]), "r"(b[1]));
}
__device__ __forceinline__ void cpa16(const void* smem_dst, const void* gmem_src) {
    uint32_t s = (uint32_t)__cvta_generic_to_shared(smem_dst);
    asm volatile("cp.async.cg.shared.global [%0], [%1], 16;" :: "r"(s), "l"(gmem_src));
}
#define CP_COMMIT() asm volatile("cp.async.commit_group;")
#define CP_WAIT1()  asm volatile("cp.async.wait_group 1;")
#define CP_WAIT0()  asm volatile("cp.async.wait_group 0;")

// ========= K1: q/k/v = X @ W^T (2048x512x512), 3-stage ring, single-sync;
//           z==0 additionally computes qr = 0.125*q@Wr and qb = 0.125*q.br;
//           all outputs stored tf32-pre-rounded ============================
#define K1_SMEM (13824 * 4)

__global__ void __launch_bounds__(256) k_qkv(const float* __restrict__ X,
                                             const float* __restrict__ Wq,
                                             const float* __restrict__ Wk,
                                             const float* __restrict__ Wv,
                                             const float* __restrict__ Wr,
                                             const float* __restrict__ br) {
    extern __shared__ float dsm[];
    const int z = blockIdx.z;
    const float* __restrict__ W = (z == 0) ? Wq : (z == 1) ? Wk : Wv;
    const int tid = threadIdx.x, lane = tid & 31, w = tid >> 5;
    const int g = lane >> 2, t = lane & 3, wm = w >> 2, wn = w & 3;
    const int m0 = blockIdx.x * 64, n0 = blockIdx.y * 64;
    const int lr = tid >> 3, lc = (tid & 7) * 4;
    float acc[2][2][4] = {};

    auto issue = [&](int ki) {
        int st = ki % 3, kt = ki * 32;
        float* Xs = dsm + st * 2304;
        float* Ws = dsm + 6912 + st * 2304;
#pragma unroll
        for (int rr = 0; rr < 2; rr++) {
            int r = lr + rr * 32;
            cpa16(&Xs[r * 36 + lc], &X[(size_t)(m0 + r) * NDM + kt + lc]);
            cpa16(&Ws[r * 36 + lc], &W[(size_t)(n0 + r) * NDM + kt + lc]);
        }
    };
    issue(0); CP_COMMIT();
    issue(1); CP_COMMIT();
    for (int ki = 0; ki < 16; ki++) {
        if (ki < 15) CP_WAIT1(); else CP_WAIT0();
        __syncthreads();
        if (ki < 14) { issue(ki + 2); CP_COMMIT(); }
        int st = ki % 3;
        const float* Xf = dsm + st * 2304;
        const float* Wf = dsm + 6912 + st * 2304;
#pragma unroll
        for (int ks = 0; ks < 4; ks++) {
            uint32_t a[2][4], bb[2][2];
#pragma unroll
            for (int mi = 0; mi < 2; mi++) {
                int r = wm * 32 + mi * 16 + g;
                a[mi][0] = f2tf(Xf[r*36 + ks*8 + t]);     a[mi][1] = f2tf(Xf[(r+8)*36 + ks*8 + t]);
                a[mi][2] = f2tf(Xf[r*36 + ks*8 + t + 4]); a[mi][3] = f2tf(Xf[(r+8)*36 + ks*8 + t + 4]);
            }
#pragma unroll
            for (int ni = 0; ni < 2; ni++) {
                int c = wn * 16 + ni * 8 + g;
                bb[ni][0] = f2tf(Wf[c*36 + ks*8 + t]); bb[ni][1] = f2tf(Wf[c*36 + ks*8 + t + 4]);
            }
#pragma unroll
            for (int mi = 0; mi < 2; mi++)
#pragma unroll
                for (int ni = 0; ni < 2; ni++) mma8(acc[mi][ni], a[mi], bb[ni]);
        }
    }
    // global store of q/k/v, tf32-pre-rounded so consumers skip cvt
#pragma unroll
    for (int mi = 0; mi < 2; mi++)
#pragma unroll
        for (int ni = 0; ni < 2; ni++) {
            int m = m0 + wm*32 + mi*16 + g, n = n0 + wn*16 + ni*8 + 2*t;
            int b = m >> 9, s = m & 511, h = n >> 6, d = n & 63, bh = b*NH + h;
            if (z == 2) {
                g_v[(bh*NDH + d)  *NS + s]     = f2tff(acc[mi][ni][0]);
                g_v[(bh*NDH + d+1)*NS + s]     = f2tff(acc[mi][ni][1]);
                g_v[(bh*NDH + d)  *NS + s + 8] = f2tff(acc[mi][ni][2]);
                g_v[(bh*NDH + d+1)*NS + s + 8] = f2tff(acc[mi][ni][3]);
            } else {
                float* o = (z == 0) ? g_q : g_k;
                float* o1 = &o[((bh*NS + s)    *NDH) + d];
                float* o2 = &o[((bh*NS + s + 8)*NDH) + d];
                o1[0]=f2tff(acc[mi][ni][0]); o1[1]=f2tff(acc[mi][ni][1]);
                o2[0]=f2tff(acc[mi][ni][2]); o2[1]=f2tff(acc[mi][ni][3]);
            }
        }
    if (z != 0) return;

    // ---- fused qr/qb epilogue (this CTA holds q[m0..m0+63][head hB][0..63]) --
    float* Qs  = dsm;            // [64][68]
    float* WrT = dsm + 6912;     // [64 r][68 d]: WrT[r][d] = Wr[d][r]
    float* brs = dsm + 11264;
    const int hB = blockIdx.y;
    __syncthreads();   // everyone done reading stage buffers
#pragma unroll
    for (int mi = 0; mi < 2; mi++)
#pragma unroll
        for (int ni = 0; ni < 2; ni++) {
            int ml = wm*32 + mi*16 + g, nl = wn*16 + ni*8 + 2*t;
            Qs[ml*68 + nl] = acc[mi][ni][0];     Qs[ml*68 + nl + 1] = acc[mi][ni][1];
            Qs[(ml+8)*68 + nl] = acc[mi][ni][2]; Qs[(ml+8)*68 + nl + 1] = acc[mi][ni][3];
        }
    for (int i = tid; i < 4096; i += 256) {
        int d = i >> 6, r = i & 63;
        WrT[r*68 + d] = Wr[i];     // coalesced read
    }
    if (tid < 64) brs[tid] = br[tid];
    __syncthreads();

    float qacc[2][2][4] = {};
#pragma unroll
    for (int ks = 0; ks < 8; ks++) {
        uint32_t a[2][4], bb[2][2];
#pragma unroll
        for (int mi = 0; mi < 2; mi++) {
            int r = wm * 32 + mi * 16 + g;
            a[mi][0] = f2tf(Qs[r*68 + ks*8 + t]);     a[mi][1] = f2tf(Qs[(r+8)*68 + ks*8 + t]);
            a[mi][2] = f2tf(Qs[r*68 + ks*8 + t + 4]); a[mi][3] = f2tf(Qs[(r+8)*68 + ks*8 + t + 4]);
        }
#pragma unroll
        for (int ni = 0; ni < 2; ni++) {
            int c = wn * 16 + ni * 8 + g;
            bb[ni][0] = f2tf(WrT[c*68 + ks*8 + t]); bb[ni][1] = f2tf(WrT[c*68 + ks*8 + t + 4]);
        }
#pragma unroll
        for (int mi = 0; mi < 2; mi++)
#pragma unroll
            for (int ni = 0; ni < 2; ni++) mma8(qacc[mi][ni], a[mi], bb[ni]);
    }
#pragma unroll
    for (int mi = 0; mi < 2; mi++)
#pragma unroll
        for (int ni = 0; ni < 2; ni++) {
            int ml = wm*32 + mi*16 + g, col = wn*16 + ni*8 + 2*t;
            int m = m0 + ml, b = m >> 9, s = m & 511;
            float* o1 = &g_qr[(((size_t)(b*NH + hB)*NS + s)     ) * NDH + col];
            float* o2 = &g_qr[(((size_t)(b*NH + hB)*NS + (s+8)) ) * NDH + col];
            o1[0] = f2tff(qacc[mi][ni][0]) * 0.125f; o1[1] = f2tff(qacc[mi][ni][1]) * 0.125f;
            o2[0] = f2tff(qacc[mi][ni][2]) * 0.125f; o2[1] = f2tff(qacc[mi][ni][3]) * 0.125f;
        }
    // qb: 4 threads per row
    {
        int row = tid >> 2, qg = tid & 3;
        float p = 0.f;
#pragma unroll
        for (int d = 0; d < 16; d++) p += Qs[row*68 + qg*16 + d] * brs[qg*16 + d];
        p += __shfl_xor_sync(0xffffffffu, p, 1);
        p += __shfl_xor_sync(0xffffffffu, p, 2);
        if (qg == 0) {
            int m = m0 + row, b = m >> 9, s = m & 511;
            g_qb[(b*NH + hB)*NS + s] = p * 0.125f;
        }
    }
}

// ======= K3: 0.125*q k^T per (b,h), scores -> [b][q][h][k]; cvt-free ========
__global__ void __launch_bounds__(256) k_qk() {
    const int bh = blockIdx.z, b = bh >> 3, h = bh & 7;
    const float* __restrict__ Q = &g_q[(size_t)bh * NS * NDH];
    const float* __restrict__ K = &g_k[(size_t)bh * NS * NDH];
    __shared__ float As[64 * 68], Bs[64 * 68];
    const int tid = threadIdx.x, lane = tid & 31, w = tid >> 5;
    const int g = lane >> 2, t = lane & 3, wm = w >> 2, wn = w & 3;
    const int m0 = blockIdx.x * 64, n0 = blockIdx.y * 64;
#pragma unroll
    for (int rr = 0; rr < 4; rr++) {
        int r = (tid >> 4) + rr * 16, c4 = (tid & 15) * 4;
        cpa16(&As[r * 68 + c4], &Q[(m0 + r) * NDH + c4]);
        cpa16(&Bs[r * 68 + c4], &K[(n0 + r) * NDH + c4]);
    }
    CP_COMMIT(); CP_WAIT0();
    __syncthreads();
    float acc[2][2][4] = {};
#pragma unroll
    for (int ks = 0; ks < 8; ks++) {
        uint32_t a[2][4], bb[2][2];
#pragma unroll
        for (int mi = 0; mi < 2; mi++) {
            int r = wm * 32 + mi * 16 + g;
            a[mi][0] = __float_as_uint(As[r*68 + ks*8 + t]);
            a[mi][1] = __float_as_uint(As[(r+8)*68 + ks*8 + t]);
            a[mi][2] = __float_as_uint(As[r*68 + ks*8 + t + 4]);
            a[mi][3] = __float_as_uint(As[(r+8)*68 + ks*8 + t + 4]);
        }
#pragma unroll
        for (int ni = 0; ni < 2; ni++) {
            int c = wn * 16 + ni * 8 + g;
            bb[ni][0] = __float_as_uint(Bs[c*68 + ks*8 + t]);
            bb[ni][1] = __float_as_uint(Bs[c*68 + ks*8 + t + 4]);
        }
#pragma unroll
        for (int mi = 0; mi < 2; mi++)
#pragma unroll
            for (int ni = 0; ni < 2; ni++) mma8(acc[mi][ni], a[mi], bb[ni]);
    }
#pragma unroll
    for (int mi = 0; mi < 2; mi++)
#pragma unroll
        for (int ni = 0; ni < 2; ni++) {
            int m = m0 + wm*32 + mi*16 + g, n = n0 + wn*16 + ni*8 + 2*t;
            float* o1 = &g_s1[((size_t)(b*NS + m)    *NH + h)*NS + n];
            float* o2 = &g_s1[((size_t)(b*NS + m + 8)*NH + h)*NS + n];
            o1[0] = acc[mi][ni][0] * 0.125f; o1[1] = acc[mi][ni][1] * 0.125f;
            o2[0] = acc[mi][ni][2] * 0.125f; o2[1] = acc[mi][ni][3] * 0.125f;
        }
}

// ===== K4: per (b,q): rel mma + scores(reg) + mask + softmax ================
// dyn smem floats: relb[2][128*68] | qrs[8*68] | qbs[8] | red[128]
#define RELW   (128 * 68)
#define OFF_QR (2 * RELW)
#define OFF_QB (OFF_QR + 8 * 68)
#define OFF_RED (OFF_QB + 8)
#define K4_SMEM ((OFF_RED + 128) * 4)   // 72,992 bytes -> 3 CTAs/SM

__global__ void __launch_bounds__(256) k_relsm(const float* __restrict__ REL,
                                               const int* __restrict__ GRAPH) {
    extern __shared__ float sm[];
    float* relb = sm;
    uint32_t* qrs = (uint32_t*)(sm + OFF_QR);
    float* qbs = sm + OFF_QB;
    float* red = sm + OFF_RED;   // [2][8 warps][8 h]

    const int q = blockIdx.x, b = blockIdx.y;
    const int tid = threadIdx.x, lane = tid & 31, w = tid >> 5;
    const int g = lane >> 2, t = lane & 3;

    const float* relrow = REL + (size_t)(b*NS + q) * NS * NDH;
    const float* scrow  = &g_s1[(size_t)(b*NS + q) * NH * NS];
    const int*   grow   = &GRAPH[(size_t)(b*NS + q) * NS];

    auto issue_rel = [&](int ch) {
        const float* src = relrow + (size_t)ch * 128 * NDH;
        float* dst = relb + (ch & 1) * RELW;
        int c4 = (tid & 15) * 4, r0 = tid >> 4;
#pragma unroll
        for (int rr = 0; rr < 8; rr++) {
            int r = r0 + rr * 16;
            cpa16(&dst[r * 68 + c4], src + (size_t)r * NDH + c4);
        }
    };
    issue_rel(0); CP_COMMIT();
    issue_rel(1); CP_COMMIT();

    // scores + graph -> registers (masked at load)
    float sc[16];
#pragma unroll
    for (int ch = 0; ch < 4; ch++) {
        int k0 = ch * 128 + w * 16;
#pragma unroll
        for (int j = 0; j < 4; j++) {
            int k = k0 + g + ((j >= 2) ? 8 : 0);
            int h = 2 * t + (j & 1);
            sc[ch*4+j] = scrow[(size_t)h*NS + k] + (1.f - (float)grow[k]) * -1e9f;
        }
    }
    if (tid < 8) qbs[tid] = g_qb[(b*NH + tid)*NS + q];
    for (int i = tid; i < 512; i += 256) {
        int h = i >> 6, r = i & 63;
        qrs[h * 68 + r] = __float_as_uint(g_qr[(size_t)((b*NH + h)*NS + q) * NDH + r]);
    }
    __syncthreads();
    uint32_t bf[8][2];
#pragma unroll
    for (int ks = 0; ks < 8; ks++) {
        bf[ks][0] = qrs[g*68 + ks*8 + t];
        bf[ks][1] = qrs[g*68 + ks*8 + t + 4];
    }
    const float qb0 = qbs[2*t], qb1 = qbs[2*t + 1];

    for (int ch = 0; ch < 4; ch++) {
        if (ch < 3) CP_WAIT1(); else CP_WAIT0();
        __syncthreads();
        const float* buf = relb + (ch & 1) * RELW;
        float c[4] = {0,0,0,0};
        int r0 = w * 16 + g;
#pragma unroll
        for (int ks = 0; ks < 8; ks++) {
            uint32_t a[4];
            a[0] = f2tf(buf[r0*68 + ks*8 + t]);     a[1] = f2tf(buf[(r0+8)*68 + ks*8 + t]);
            a[2] = f2tf(buf[r0*68 + ks*8 + t + 4]); a[3] = f2tf(buf[(r0+8)*68 + ks*8 + t + 4]);
            mma8(c, a, bf[ks]);
        }
#pragma unroll
        for (int j = 0; j < 4; j++)
            sc[ch*4+j] += c[j] + ((j & 1) ? qb1 : qb0);
        __syncthreads();
        if (ch < 2) { issue_rel(ch + 2); CP_COMMIT(); }
    }
    // softmax: even sc index -> h=2t, odd -> h=2t+1
    float mx0 = -3e38f, mx1 = -3e38f;
#pragma unroll
    for (int i = 0; i < 16; i++) { if (i & 1) mx1 = fmaxf(mx1, sc[i]); else mx0 = fmaxf(mx0, sc[i]); }
#pragma unroll
    for (int o = 4; o < 32; o <<= 1) {
        mx0 = fmaxf(mx0, __shfl_xor_sync(0xffffffffu, mx0, o));
        mx1 = fmaxf(mx1, __shfl_xor_sync(0xffffffffu, mx1, o));
    }
    if (g == 0) { red[w*8 + 2*t] = mx0; red[w*8 + 2*t+1] = mx1; }
    __syncthreads();
    float fm0 = -3e38f, fm1 = -3e38f;
#pragma unroll
    for (int ww = 0; ww < 8; ww++) {
        fm0 = fmaxf(fm0, red[ww*8 + 2*t]); fm1 = fmaxf(fm1, red[ww*8 + 2*t+1]);
    }
    float s0 = 0.f, s1 = 0.f;
#pragma unroll
    for (int i = 0; i < 16; i++) {
        float e = __expf(sc[i] - ((i & 1) ? fm1 : fm0));
        sc[i] = e;
        if (i & 1) s1 += e; else s0 += e;
    }
#pragma unroll
    for (int o = 4; o < 32; o <<= 1) {
        s0 += __shfl_xor_sync(0xffffffffu, s0, o);
        s1 += __shfl_xor_sync(0xffffffffu, s1, o);
    }
    if (g == 0) { red[64 + w*8 + 2*t] = s0; red[64 + w*8 + 2*t+1] = s1; }
    __syncthreads();
    float ts0 = 0.f, ts1 = 0.f;
#pragma unroll
    for (int ww = 0; ww < 8; ww++) { ts0 += red[64 + ww*8 + 2*t]; ts1 += red[64 + ww*8 + 2*t+1]; }
    float r0i = 1.f / ts0, r1i = 1.f / ts1;

    // stage probs [h][k] into relb (tf32-rounded so k_pv skips cvt)
    float* pbuf = relb;
    __syncthreads();
#pragma unroll
    for (int ch = 0; ch < 4; ch++) {
        int k0 = ch * 128 + w * 16;
#pragma unroll
        for (int j = 0; j < 4; j++) {
            int k = k0 + g + ((j >= 2) ? 8 : 0);
            int h = 2 * t + (j & 1);
            pbuf[h * NS + k] = f2tff(sc[ch*4+j] * ((j & 1) ? r1i : r0i));
        }
    }
    __syncthreads();
    float* pout = &g_p[(size_t)(b*NS + q) * NH * NS];
    for (int i = tid; i < 1024; i += 256)
        *(float4*)&pout[i * 4] = *(const float4*)&pbuf[i * 4];
}

// ========= K5: out = probs @ v per (b,h), BM=64, 3-stage ring, cvt-free =====
#define K5_SMEM (3 * 2 * 2304 * 4)   // 55,296 bytes

__global__ void __launch_bounds__(256) k_pv(float* __restrict__ OUT) {
    extern __shared__ float dsm[];
    const int bh = blockIdx.z, b = bh >> 3, h = bh & 7;
    const float* __restrict__ VT = &g_v[(size_t)bh * NDH * NS];
    const int tid = threadIdx.x, lane = tid & 31, w = tid >> 5;
    const int g = lane >> 2, t = lane & 3, wm = w >> 2, wn = w & 3;
    const int m0 = blockIdx.x * 64;
    const int lr = tid >> 3, lc = (tid & 7) * 4;
    float acc[2][2][4] = {};

    auto issue = [&](int ki) {
        int st = ki % 3, kt = ki * 32;
        float* As = dsm + st * 2304;
        float* Bs = dsm + 6912 + st * 2304;
#pragma unroll
        for (int rr = 0; rr < 2; rr++) {
            int r = lr + rr * 32;
            cpa16(&As[r * 36 + lc], &g_p[((size_t)(b*NS + m0 + r)*NH + h)*NS + kt + lc]);
            cpa16(&Bs[r * 36 + lc], &VT[(size_t)r * NS + kt + lc]);
        }
    };
    issue(0); CP_COMMIT();
    issue(1); CP_COMMIT();
    for (int ki = 0; ki < 16; ki++) {
        if (ki < 15) CP_WAIT1(); else CP_WAIT0();
        __syncthreads();
        if (ki < 14) { issue(ki + 2); CP_COMMIT(); }
        int st = ki % 3;
        const float* Af = dsm + st * 2304;
        const float* Bf = dsm + 6912 + st * 2304;
#pragma unroll
        for (int ks = 0; ks < 4; ks++) {
            uint32_t a[2][4], bb[2][2];
#pragma unroll
            for (int mi = 0; mi < 2; mi++) {
                int r = wm * 32 + mi * 16 + g;
                a[mi][0] = __float_as_uint(Af[r*36 + ks*8 + t]);
                a[mi][1] = __float_as_uint(Af[(r+8)*36 + ks*8 + t]);
                a[mi][2] = __float_as_uint(Af[r*36 + ks*8 + t + 4]);
                a[mi][3] = __float_as_uint(Af[(r+8)*36 + ks*8 + t + 4]);
            }
#pragma unroll
            for (int ni = 0; ni < 2; ni++) {
                int c = wn * 16 + ni * 8 + g;
                bb[ni][0] = __float_as_uint(Bf[c*36 + ks*8 + t]);
                bb[ni][1] = __float_as_uint(Bf[c*36 + ks*8 + t + 4]);
            }
#pragma unroll
            for (int mi = 0; mi < 2; mi++)
#pragma unroll
                for (int ni = 0; ni < 2; ni++) mma8(acc[mi][ni], a[mi], bb[ni]);
        }
    }
#pragma unroll
    for (int mi = 0; mi < 2; mi++)
#pragma unroll
        for (int ni = 0; ni < 2; ni++) {
            int m = m0 + wm*32 + mi*16 + g, n = wn*16 + ni*8 + 2*t;
            float* o1 = &OUT[(size_t)(b*NS + m)    *NDM + h*NDH + n];
            float* o2 = &OUT[(size_t)(b*NS + m + 8)*NDM + h*NDH + n];
            o1[0]=acc[mi][ni][0]; o1[1]=acc[mi][ni][1];
            o2[0]=acc[mi][ni][2]; o2[1]=acc[mi][ni][3];
        }
}

extern "C" void kernel_launch(void* const* d_in, const int* in_sizes, int n_in,
                              void* d_out, int out_size) {
    const float* X     = (const float*)d_in[0];
    const int*   GRAPH = (const int*)  d_in[1];
    const float* REL   = (const float*)d_in[2];
    const float* Wq    = (const float*)d_in[3];
    const float* Wk    = (const float*)d_in[4];
    const float* Wv    = (const float*)d_in[5];
    const float* Wr    = (const float*)d_in[6];
    const float* br    = (const float*)d_in[7];
    float* OUT = (float*)d_out;

    static bool attr_set = false;
    if (!attr_set) {
        cudaFuncSetAttribute(k_qkv,   cudaFuncAttributeMaxDynamicSharedMemorySize, K1_SMEM);
        cudaFuncSetAttribute(k_relsm, cudaFuncAttributeMaxDynamicSharedMemorySize, K4_SMEM);
        cudaFuncSetAttribute(k_pv,    cudaFuncAttributeMaxDynamicSharedMemorySize, K5_SMEM);
        attr_set = true;
    }

    k_qkv  <<<dim3(32, 8, 3), 256, K1_SMEM>>>(X, Wq, Wk, Wv, Wr, br);
    k_qk   <<<dim3(8, 8, 32), 256>>>();
    k_relsm<<<dim3(512, 4), 256, K4_SMEM>>>(REL, GRAPH);
    k_pv   <<<dim3(8, 1, 32), 256, K5_SMEM>>>(OUT);
}

// round 13
// speedup vs baseline: 1.1141x; 1.0163x over previous
#include <cuda_runtime.h>
#include <cstdint>
#include <cstddef>

#define NB 4
#define NS 512
#define NH 8
#define NDH 64
#define NDM 512
#define NBH 32

// ---- scratch (device globals; no allocation) ----
__device__ float g_q [NBH * NS * NDH];        // tf32-rounded
__device__ float g_k [NBH * NS * NDH];        // tf32-rounded
__device__ float g_v [NBH * NDH * NS];        // transposed [bh][d][s], tf32-rounded
__device__ float g_qr[NBH * NS * NDH];        // tf32-rounded, pre-scaled by 0.125
__device__ float g_qb[NBH * NS];              // pre-scaled by 0.125
__device__ float g_s1[(size_t)NB * NS * NH * NS];  // scores [b][q][h][k], pre-scaled
__device__ float g_p [(size_t)NB * NS * NH * NS];  // probs  [b][q][h][k], tf32-rounded

__device__ __forceinline__ uint32_t f2tf(float x) {
    uint32_t r; asm("cvt.rna.tf32.f32 %0, %1;" : "=r"(r) : "f"(x)); return r;
}
__device__ __forceinline__ float f2tff(float x) { return __uint_as_float(f2tf(x)); }
__device__ __forceinline__ void mma8(float* d, const uint32_t* a, const uint32_t* b) {
    asm volatile(
        "mma.sync.aligned.m16n8k8.row.col.f32.tf32.tf32.f32 "
        "{%0,%1,%2,%3}, {%4,%5,%6,%7}, {%8,%9}, {%0,%1,%2,%3};"
        : "+f"(d[0]), "+f"(d[1]), "+f"(d[2]), "+f"(d[3])
        : "r"(a[0]), "r"(a[1]), "r"(a[2]), "r"(a[3]), "r"(b[0]), "r"(b[1]));
}
__device__ __forceinline__ void cpa16(const void* smem_dst, const void* gmem_src) {
    uint32_t s = (uint32_t)__cvta_generic_to_shared(smem_dst);
    asm volatile("cp.async.cg.shared.global [%0], [%1], 16;" :: "r"(s), "l"(gmem_src));
}
#define CP_COMMIT() asm volatile("cp.async.commit_group;")
#define CP_WAIT1()  asm volatile("cp.async.wait_group 1;")
#define CP_WAIT0()  asm volatile("cp.async.wait_group 0;")

// ========= K1: q/k/v = X @ W^T (2048x512x512), 3-stage ring, single-sync;
//           X/W fed to mma as raw bits (tf32 truncation) -> cvt-free mainloop;
//           z==0 additionally computes qr = 0.125*q@Wr and qb = 0.125*q.br;
//           outputs stored tf32-RN-rounded ================================
#define K1_SMEM (13824 * 4)

__global__ void __launch_bounds__(256) k_qkv(const float* __restrict__ X,
                                             const float* __restrict__ Wq,
                                             const float* __restrict__ Wk,
                                             const float* __restrict__ Wv,
                                             const float* __restrict__ Wr,
                                             const float* __restrict__ br) {
    extern __shared__ float dsm[];
    const int z = blockIdx.z;
    const float* __restrict__ W = (z == 0) ? Wq : (z == 1) ? Wk : Wv;
    const int tid = threadIdx.x, lane = tid & 31, w = tid >> 5;
    const int g = lane >> 2, t = lane & 3, wm = w >> 2, wn = w & 3;
    const int m0 = blockIdx.x * 64, n0 = blockIdx.y * 64;
    const int lr = tid >> 3, lc = (tid & 7) * 4;
    float acc[2][2][4] = {};

    auto issue = [&](int ki) {
        int st = ki % 3, kt = ki * 32;
        float* Xs = dsm + st * 2304;
        float* Ws = dsm + 6912 + st * 2304;
#pragma unroll
        for (int rr = 0; rr < 2; rr++) {
            int r = lr + rr * 32;
            cpa16(&Xs[r * 36 + lc], &X[(size_t)(m0 + r) * NDM + kt + lc]);
            cpa16(&Ws[r * 36 + lc], &W[(size_t)(n0 + r) * NDM + kt + lc]);
        }
    };
    issue(0); CP_COMMIT();
    issue(1); CP_COMMIT();
    for (int ki = 0; ki < 16; ki++) {
        if (ki < 15) CP_WAIT1(); else CP_WAIT0();
        __syncthreads();
        if (ki < 14) { issue(ki + 2); CP_COMMIT(); }
        int st = ki % 3;
        const float* Xf = dsm + st * 2304;
        const float* Wf = dsm + 6912 + st * 2304;
#pragma unroll
        for (int ks = 0; ks < 4; ks++) {
            uint32_t a[2][4], bb[2][2];
#pragma unroll
            for (int mi = 0; mi < 2; mi++) {
                int r = wm * 32 + mi * 16 + g;
                a[mi][0] = __float_as_uint(Xf[r*36 + ks*8 + t]);
                a[mi][1] = __float_as_uint(Xf[(r+8)*36 + ks*8 + t]);
                a[mi][2] = __float_as_uint(Xf[r*36 + ks*8 + t + 4]);
                a[mi][3] = __float_as_uint(Xf[(r+8)*36 + ks*8 + t + 4]);
            }
#pragma unroll
            for (int ni = 0; ni < 2; ni++) {
                int c = wn * 16 + ni * 8 + g;
                bb[ni][0] = __float_as_uint(Wf[c*36 + ks*8 + t]);
                bb[ni][1] = __float_as_uint(Wf[c*36 + ks*8 + t + 4]);
            }
#pragma unroll
            for (int mi = 0; mi < 2; mi++)
#pragma unroll
                for (int ni = 0; ni < 2; ni++) mma8(acc[mi][ni], a[mi], bb[ni]);
        }
    }
    // global store of q/k/v, tf32-RN-rounded so consumers skip cvt
#pragma unroll
    for (int mi = 0; mi < 2; mi++)
#pragma unroll
        for (int ni = 0; ni < 2; ni++) {
            int m = m0 + wm*32 + mi*16 + g, n = n0 + wn*16 + ni*8 + 2*t;
            int b = m >> 9, s = m & 511, h = n >> 6, d = n & 63, bh = b*NH + h;
            if (z == 2) {
                g_v[(bh*NDH + d)  *NS + s]     = f2tff(acc[mi][ni][0]);
                g_v[(bh*NDH + d+1)*NS + s]     = f2tff(acc[mi][ni][1]);
                g_v[(bh*NDH + d)  *NS + s + 8] = f2tff(acc[mi][ni][2]);
                g_v[(bh*NDH + d+1)*NS + s + 8] = f2tff(acc[mi][ni][3]);
            } else {
                float* o = (z == 0) ? g_q : g_k;
                float* o1 = &o[((bh*NS + s)    *NDH) + d];
                float* o2 = &o[((bh*NS + s + 8)*NDH) + d];
                o1[0]=f2tff(acc[mi][ni][0]); o1[1]=f2tff(acc[mi][ni][1]);
                o2[0]=f2tff(acc[mi][ni][2]); o2[1]=f2tff(acc[mi][ni][3]);
            }
        }
    if (z != 0) return;

    // ---- fused qr/qb epilogue (this CTA holds q[m0..m0+63][head hB][0..63]) --
    float* Qs  = dsm;            // [64][68]
    float* WrT = dsm + 6912;     // [64 r][68 d]: WrT[r][d] = Wr[d][r]
    float* brs = dsm + 11264;
    const int hB = blockIdx.y;
    __syncthreads();   // everyone done reading stage buffers
#pragma unroll
    for (int mi = 0; mi < 2; mi++)
#pragma unroll
        for (int ni = 0; ni < 2; ni++) {
            int ml = wm*32 + mi*16 + g, nl = wn*16 + ni*8 + 2*t;
            Qs[ml*68 + nl] = acc[mi][ni][0];     Qs[ml*68 + nl + 1] = acc[mi][ni][1];
            Qs[(ml+8)*68 + nl] = acc[mi][ni][2]; Qs[(ml+8)*68 + nl + 1] = acc[mi][ni][3];
        }
    for (int i = tid; i < 4096; i += 256) {
        int d = i >> 6, r = i & 63;
        WrT[r*68 + d] = Wr[i];     // coalesced read
    }
    if (tid < 64) brs[tid] = br[tid];
    __syncthreads();

    float qacc[2][2][4] = {};
#pragma unroll
    for (int ks = 0; ks < 8; ks++) {
        uint32_t a[2][4], bb[2][2];
#pragma unroll
        for (int mi = 0; mi < 2; mi++) {
            int r = wm * 32 + mi * 16 + g;
            a[mi][0] = f2tf(Qs[r*68 + ks*8 + t]);     a[mi][1] = f2tf(Qs[(r+8)*68 + ks*8 + t]);
            a[mi][2] = f2tf(Qs[r*68 + ks*8 + t + 4]); a[mi][3] = f2tf(Qs[(r+8)*68 + ks*8 + t + 4]);
        }
#pragma unroll
        for (int ni = 0; ni < 2; ni++) {
            int c = wn * 16 + ni * 8 + g;
            bb[ni][0] = f2tf(WrT[c*68 + ks*8 + t]); bb[ni][1] = f2tf(WrT[c*68 + ks*8 + t + 4]);
        }
#pragma unroll
        for (int mi = 0; mi < 2; mi++)
#pragma unroll
            for (int ni = 0; ni < 2; ni++) mma8(qacc[mi][ni], a[mi], bb[ni]);
    }
#pragma unroll
    for (int mi = 0; mi < 2; mi++)
#pragma unroll
        for (int ni = 0; ni < 2; ni++) {
            int ml = wm*32 + mi*16 + g, col = wn*16 + ni*8 + 2*t;
            int m = m0 + ml, b = m >> 9, s = m & 511;
            float* o1 = &g_qr[(((size_t)(b*NH + hB)*NS + s)     ) * NDH + col];
            float* o2 = &g_qr[(((size_t)(b*NH + hB)*NS + (s+8)) ) * NDH + col];
            o1[0] = f2tff(qacc[mi][ni][0]) * 0.125f; o1[1] = f2tff(qacc[mi][ni][1]) * 0.125f;
            o2[0] = f2tff(qacc[mi][ni][2]) * 0.125f; o2[1] = f2tff(qacc[mi][ni][3]) * 0.125f;
        }
    // qb: 4 threads per row
    {
        int row = tid >> 2, qg = tid & 3;
        float p = 0.f;
#pragma unroll
        for (int d = 0; d < 16; d++) p += Qs[row*68 + qg*16 + d] * brs[qg*16 + d];
        p += __shfl_xor_sync(0xffffffffu, p, 1);
        p += __shfl_xor_sync(0xffffffffu, p, 2);
        if (qg == 0) {
            int m = m0 + row, b = m >> 9, s = m & 511;
            g_qb[(b*NH + hB)*NS + s] = p * 0.125f;
        }
    }
}

// ======= K3: 0.125*q k^T per (b,h), scores -> [b][q][h][k]; cvt-free ========
__global__ void __launch_bounds__(256) k_qk() {
    const int bh = blockIdx.z, b = bh >> 3, h = bh & 7;
    const float* __restrict__ Q = &g_q[(size_t)bh * NS * NDH];
    const float* __restrict__ K = &g_k[(size_t)bh * NS * NDH];
    __shared__ float As[64 * 68], Bs[64 * 68];
    const int tid = threadIdx.x, lane = tid & 31, w = tid >> 5;
    const int g = lane >> 2, t = lane & 3, wm = w >> 2, wn = w & 3;
    const int m0 = blockIdx.x * 64, n0 = blockIdx.y * 64;
#pragma unroll
    for (int rr = 0; rr < 4; rr++) {
        int r = (tid >> 4) + rr * 16, c4 = (tid & 15) * 4;
        cpa16(&As[r * 68 + c4], &Q[(m0 + r) * NDH + c4]);
        cpa16(&Bs[r * 68 + c4], &K[(n0 + r) * NDH + c4]);
    }
    CP_COMMIT(); CP_WAIT0();
    __syncthreads();
    float acc[2][2][4] = {};
#pragma unroll
    for (int ks = 0; ks < 8; ks++) {
        uint32_t a[2][4], bb[2][2];
#pragma unroll
        for (int mi = 0; mi < 2; mi++) {
            int r = wm * 32 + mi * 16 + g;
            a[mi][0] = __float_as_uint(As[r*68 + ks*8 + t]);
            a[mi][1] = __float_as_uint(As[(r+8)*68 + ks*8 + t]);
            a[mi][2] = __float_as_uint(As[r*68 + ks*8 + t + 4]);
            a[mi][3] = __float_as_uint(As[(r+8)*68 + ks*8 + t + 4]);
        }
#pragma unroll
        for (int ni = 0; ni < 2; ni++) {
            int c = wn * 16 + ni * 8 + g;
            bb[ni][0] = __float_as_uint(Bs[c*68 + ks*8 + t]);
            bb[ni][1] = __float_as_uint(Bs[c*68 + ks*8 + t + 4]);
        }
#pragma unroll
        for (int mi = 0; mi < 2; mi++)
#pragma unroll
            for (int ni = 0; ni < 2; ni++) mma8(acc[mi][ni], a[mi], bb[ni]);
    }
#pragma unroll
    for (int mi = 0; mi < 2; mi++)
#pragma unroll
        for (int ni = 0; ni < 2; ni++) {
            int m = m0 + wm*32 + mi*16 + g, n = n0 + wn*16 + ni*8 + 2*t;
            float* o1 = &g_s1[((size_t)(b*NS + m)    *NH + h)*NS + n];
            float* o2 = &g_s1[((size_t)(b*NS + m + 8)*NH + h)*NS + n];
            o1[0] = acc[mi][ni][0] * 0.125f; o1[1] = acc[mi][ni][1] * 0.125f;
            o2[0] = acc[mi][ni][2] * 0.125f; o2[1] = acc[mi][ni][3] * 0.125f;
        }
}

// ===== K4: per (b,q): rel mma + scores(reg) + mask + softmax ================
// rel fed to mma as raw bits (tf32 truncation) -> cvt-free chunk loop
// dyn smem floats: relb[2][128*68] | qrs[8*68] | qbs[8] | red[128]
#define RELW   (128 * 68)
#define OFF_QR (2 * RELW)
#define OFF_QB (OFF_QR + 8 * 68)
#define OFF_RED (OFF_QB + 8)
#define K4_SMEM ((OFF_RED + 128) * 4)   // 72,992 bytes -> 3 CTAs/SM

__global__ void __launch_bounds__(256) k_relsm(const float* __restrict__ REL,
                                               const int* __restrict__ GRAPH) {
    extern __shared__ float sm[];
    float* relb = sm;
    uint32_t* qrs = (uint32_t*)(sm + OFF_QR);
    float* qbs = sm + OFF_QB;
    float* red = sm + OFF_RED;   // [2][8 warps][8 h]

    const int q = blockIdx.x, b = blockIdx.y;
    const int tid = threadIdx.x, lane = tid & 31, w = tid >> 5;
    const int g = lane >> 2, t = lane & 3;

    const float* relrow = REL + (size_t)(b*NS + q) * NS * NDH;
    const float* scrow  = &g_s1[(size_t)(b*NS + q) * NH * NS];
    const int*   grow   = &GRAPH[(size_t)(b*NS + q) * NS];

    auto issue_rel = [&](int ch) {
        const float* src = relrow + (size_t)ch * 128 * NDH;
        float* dst = relb + (ch & 1) * RELW;
        int c4 = (tid & 15) * 4, r0 = tid >> 4;
#pragma unroll
        for (int rr = 0; rr < 8; rr++) {
            int r = r0 + rr * 16;
            cpa16(&dst[r * 68 + c4], src + (size_t)r * NDH + c4);
        }
    };
    issue_rel(0); CP_COMMIT();
    issue_rel(1); CP_COMMIT();

    // scores + graph -> registers (masked at load)
    float sc[16];
#pragma unroll
    for (int ch = 0; ch < 4; ch++) {
        int k0 = ch * 128 + w * 16;
#pragma unroll
        for (int j = 0; j < 4; j++) {
            int k = k0 + g + ((j >= 2) ? 8 : 0);
            int h = 2 * t + (j & 1);
            sc[ch*4+j] = scrow[(size_t)h*NS + k] + (1.f - (float)grow[k]) * -1e9f;
        }
    }
    if (tid < 8) qbs[tid] = g_qb[(b*NH + tid)*NS + q];
    for (int i = tid; i < 512; i += 256) {
        int h = i >> 6, r = i & 63;
        qrs[h * 68 + r] = __float_as_uint(g_qr[(size_t)((b*NH + h)*NS + q) * NDH + r]);
    }
    __syncthreads();
    uint32_t bf[8][2];
#pragma unroll
    for (int ks = 0; ks < 8; ks++) {
        bf[ks][0] = qrs[g*68 + ks*8 + t];
        bf[ks][1] = qrs[g*68 + ks*8 + t + 4];
    }
    const float qb0 = qbs[2*t], qb1 = qbs[2*t + 1];

    for (int ch = 0; ch < 4; ch++) {
        if (ch < 3) CP_WAIT1(); else CP_WAIT0();
        __syncthreads();
        const float* buf = relb + (ch & 1) * RELW;
        float c[4] = {0,0,0,0};
        int r0 = w * 16 + g;
#pragma unroll
        for (int ks = 0; ks < 8; ks++) {
            uint32_t a[4];
            a[0] = __float_as_uint(buf[r0*68 + ks*8 + t]);
            a[1] = __float_as_uint(buf[(r0+8)*68 + ks*8 + t]);
            a[2] = __float_as_uint(buf[r0*68 + ks*8 + t + 4]);
            a[3] = __float_as_uint(buf[(r0+8)*68 + ks*8 + t + 4]);
            mma8(c, a, bf[ks]);
        }
#pragma unroll
        for (int j = 0; j < 4; j++)
            sc[ch*4+j] += c[j] + ((j & 1) ? qb1 : qb0);
        __syncthreads();
        if (ch < 2) { issue_rel(ch + 2); CP_COMMIT(); }
    }
    // softmax: even sc index -> h=2t, odd -> h=2t+1
    float mx0 = -3e38f, mx1 = -3e38f;
#pragma unroll
    for (int i = 0; i < 16; i++) { if (i & 1) mx1 = fmaxf(mx1, sc[i]); else mx0 = fmaxf(mx0, sc[i]); }
#pragma unroll
    for (int o = 4; o < 32; o <<= 1) {
        mx0 = fmaxf(mx0, __shfl_xor_sync(0xffffffffu, mx0, o));
        mx1 = fmaxf(mx1, __shfl_xor_sync(0xffffffffu, mx1, o));
    }
    if (g == 0) { red[w*8 + 2*t] = mx0; red[w*8 + 2*t+1] = mx1; }
    __syncthreads();
    float fm0 = -3e38f, fm1 = -3e38f;
#pragma unroll
    for (int ww = 0; ww < 8; ww++) {
        fm0 = fmaxf(fm0, red[ww*8 + 2*t]); fm1 = fmaxf(fm1, red[ww*8 + 2*t+1]);
    }
    float s0 = 0.f, s1 = 0.f;
#pragma unroll
    for (int i = 0; i < 16; i++) {
        float e = __expf(sc[i] - ((i & 1) ? fm1 : fm0));
        sc[i] = e;
        if (i & 1) s1 += e; else s0 += e;
    }
#pragma unroll
    for (int o = 4; o < 32; o <<= 1) {
        s0 += __shfl_xor_sync(0xffffffffu, s0, o);
        s1 += __shfl_xor_sync(0xffffffffu, s1, o);
    }
    if (g == 0) { red[64 + w*8 + 2*t] = s0; red[64 + w*8 + 2*t+1] = s1; }
    __syncthreads();
    float ts0 = 0.f, ts1 = 0.f;
#pragma unroll
    for (int ww = 0; ww < 8; ww++) { ts0 += red[64 + ww*8 + 2*t]; ts1 += red[64 + ww*8 + 2*t+1]; }
    float r0i = 1.f / ts0, r1i = 1.f / ts1;

    // stage probs [h][k] into relb (tf32-RN-rounded so k_pv skips cvt)
    float* pbuf = relb;
    __syncthreads();
#pragma unroll
    for (int ch = 0; ch < 4; ch++) {
        int k0 = ch * 128 + w * 16;
#pragma unroll
        for (int j = 0; j < 4; j++) {
            int k = k0 + g + ((j >= 2) ? 8 : 0);
            int h = 2 * t + (j & 1);
            pbuf[h * NS + k] = f2tff(sc[ch*4+j] * ((j & 1) ? r1i : r0i));
        }
    }
    __syncthreads();
    float* pout = &g_p[(size_t)(b*NS + q) * NH * NS];
    for (int i = tid; i < 1024; i += 256)
        *(float4*)&pout[i * 4] = *(const float4*)&pbuf[i * 4];
}

// ========= K5: out = probs @ v per (b,h), BM=64, 3-stage ring, cvt-free =====
#define K5_SMEM (3 * 2 * 2304 * 4)   // 55,296 bytes

__global__ void __launch_bounds__(256) k_pv(float* __restrict__ OUT) {
    extern __shared__ float dsm[];
    const int bh = blockIdx.z, b = bh >> 3, h = bh & 7;
    const float* __restrict__ VT = &g_v[(size_t)bh * NDH * NS];
    const int tid = threadIdx.x, lane = tid & 31, w = tid >> 5;
    const int g = lane >> 2, t = lane & 3, wm = w >> 2, wn = w & 3;
    const int m0 = blockIdx.x * 64;
    const int lr = tid >> 3, lc = (tid & 7) * 4;
    float acc[2][2][4] = {};

    auto issue = [&](int ki) {
        int st = ki % 3, kt = ki * 32;
        float* As = dsm + st * 2304;
        float* Bs = dsm + 6912 + st * 2304;
#pragma unroll
        for (int rr = 0; rr < 2; rr++) {
            int r = lr + rr * 32;
            cpa16(&As[r * 36 + lc], &g_p[((size_t)(b*NS + m0 + r)*NH + h)*NS + kt + lc]);
            cpa16(&Bs[r * 36 + lc], &VT[(size_t)r * NS + kt + lc]);
        }
    };
    issue(0); CP_COMMIT();
    issue(1); CP_COMMIT();
    for (int ki = 0; ki < 16; ki++) {
        if (ki < 15) CP_WAIT1(); else CP_WAIT0();
        __syncthreads();
        if (ki < 14) { issue(ki + 2); CP_COMMIT(); }
        int st = ki % 3;
        const float* Af = dsm + st * 2304;
        const float* Bf = dsm + 6912 + st * 2304;
#pragma unroll
        for (int ks = 0; ks < 4; ks++) {
            uint32_t a[2][4], bb[2][2];
#pragma unroll
            for (int mi = 0; mi < 2; mi++) {
                int r = wm * 32 + mi * 16 + g;
                a[mi][0] = __float_as_uint(Af[r*36 + ks*8 + t]);
                a[mi][1] = __float_as_uint(Af[(r+8)*36 + ks*8 + t]);
                a[mi][2] = __float_as_uint(Af[r*36 + ks*8 + t + 4]);
                a[mi][3] = __float_as_uint(Af[(r+8)*36 + ks*8 + t + 4]);
            }
#pragma unroll
            for (int ni = 0; ni < 2; ni++) {
                int c = wn * 16 + ni * 8 + g;
                bb[ni][0] = __float_as_uint(Bf[c*36 + ks*8 + t]);
                bb[ni][1] = __float_as_uint(Bf[c*36 + ks*8 + t + 4]);
            }
#pragma unroll
            for (int mi = 0; mi < 2; mi++)
#pragma unroll
                for (int ni = 0; ni < 2; ni++) mma8(acc[mi][ni], a[mi], bb[ni]);
        }
    }
#pragma unroll
    for (int mi = 0; mi < 2; mi++)
#pragma unroll
        for (int ni = 0; ni < 2; ni++) {
            int m = m0 + wm*32 + mi*16 + g, n = wn*16 + ni*8 + 2*t;
            float* o1 = &OUT[(size_t)(b*NS + m)    *NDM + h*NDH + n];
            float* o2 = &OUT[(size_t)(b*NS + m + 8)*NDM + h*NDH + n];
            o1[0]=acc[mi][ni][0]; o1[1]=acc[mi][ni][1];
            o2[0]=acc[mi][ni][2]; o2[1]=acc[mi][ni][3];
        }
}

extern "C" void kernel_launch(void* const* d_in, const int* in_sizes, int n_in,
                              void* d_out, int out_size) {
    const float* X     = (const float*)d_in[0];
    const int*   GRAPH = (const int*)  d_in[1];
    const float* REL   = (const float*)d_in[2];
    const float* Wq    = (const float*)d_in[3];
    const float* Wk    = (const float*)d_in[4];
    const float* Wv    = (const float*)d_in[5];
    const float* Wr    = (const float*)d_in[6];
    const float* br    = (const float*)d_in[7];
    float* OUT = (float*)d_out;

    static bool attr_set = false;
    if (!attr_set) {
        cudaFuncSetAttribute(k_qkv,   cudaFuncAttributeMaxDynamicSharedMemorySize, K1_SMEM);
        cudaFuncSetAttribute(k_relsm, cudaFuncAttributeMaxDynamicSharedMemorySize, K4_SMEM);
        cudaFuncSetAttribute(k_pv,    cudaFuncAttributeMaxDynamicSharedMemorySize, K5_SMEM);
        attr_set = true;
    }

    k_qkv  <<<dim3(32, 8, 3), 256, K1_SMEM>>>(X, Wq, Wk, Wv, Wr, br);
    k_qk   <<<dim3(8, 8, 32), 256>>>();
    k_relsm<<<dim3(512, 4), 256, K4_SMEM>>>(REL, GRAPH);
    k_pv   <<<dim3(8, 1, 32), 256, K5_SMEM>>>(OUT);
}

// round 14
// speedup vs baseline: 1.1279x; 1.0123x over previous
#include <cuda_runtime.h>
#include <cstdint>
#include <cstddef>

#define NB 4
#define NS 512
#define NH 8
#define NDH 64
#define NDM 512
#define NBH 32

// ---- scratch (device globals; no allocation) ----
__device__ float g_q [NBH * NS * NDH];        // tf32-rounded
__device__ float g_k [NBH * NS * NDH];        // tf32-rounded
__device__ float g_v [NBH * NDH * NS];        // transposed [bh][d][s], tf32-rounded
__device__ float g_qr[NBH * NS * NDH];        // tf32-rounded, pre-scaled by 0.125
__device__ float g_qb[NBH * NS];              // pre-scaled by 0.125
__device__ float g_s1[(size_t)NB * NS * NH * NS];  // scores [b][q][h][k], pre-scaled
__device__ float g_p [(size_t)NB * NS * NH * NS];  // probs  [b][q][h][k], tf32-rounded

__device__ __forceinline__ uint32_t f2tf(float x) {
    uint32_t r; asm("cvt.rna.tf32.f32 %0, %1;" : "=r"(r) : "f"(x)); return r;
}
__device__ __forceinline__ float f2tff(float x) { return __uint_as_float(f2tf(x)); }
__device__ __forceinline__ void mma8(float* d, const uint32_t* a, const uint32_t* b) {
    asm volatile(
        "mma.sync.aligned.m16n8k8.row.col.f32.tf32.tf32.f32 "
        "{%0,%1,%2,%3}, {%4,%5,%6,%7}, {%8,%9}, {%0,%1,%2,%3};"
        : "+f"(d[0]), "+f"(d[1]), "+f"(d[2]), "+f"(d[3])
        : "r"(a[0]), "r"(a[1]), "r"(a[2]), "r"(a[3]), "r"(b[0]), "r"(b[1]));
}
__device__ __forceinline__ void cpa16(const void* smem_dst, const void* gmem_src) {
    uint32_t s = (uint32_t)__cvta_generic_to_shared(smem_dst);
    asm volatile("cp.async.cg.shared.global [%0], [%1], 16;" :: "r"(s), "l"(gmem_src));
}
#define CP_COMMIT() asm volatile("cp.async.commit_group;")
#define CP_WAIT1()  asm volatile("cp.async.wait_group 1;")
#define CP_WAIT0()  asm volatile("cp.async.wait_group 0;")

// ========= K1: q/k/v = X @ W^T (2048x512x512), BM=128 BN=64, warp tile 32x32,
//           3-stage ring, single-sync, truncation-mode tf32 (raw bits);
//           z==0 additionally computes qr = 0.125*q@Wr and qb = 0.125*q.br ===
// dyn smem floats: Xs 3x4608 at [0,13824), Ws 3x2304 at [13824,20736)
// epilogue reuse: Qs = [0, 8704), WrT = [13824, 18176), brs = [18176, 18240)
#define K1_SMEM (20736 * 4)

__global__ void __launch_bounds__(256) k_qkv(const float* __restrict__ X,
                                             const float* __restrict__ Wq,
                                             const float* __restrict__ Wk,
                                             const float* __restrict__ Wv,
                                             const float* __restrict__ Wr,
                                             const float* __restrict__ br) {
    extern __shared__ float dsm[];
    const int z = blockIdx.z;
    const float* __restrict__ W = (z == 0) ? Wq : (z == 1) ? Wk : Wv;
    const int tid = threadIdx.x, lane = tid & 31, w = tid >> 5;
    const int g = lane >> 2, t = lane & 3;
    const int wm = w >> 1, wn = w & 1;           // 4 x 2 warp grid, 32x32 tiles
    const int m0 = blockIdx.x * 128, n0 = blockIdx.y * 64;
    const int lr = tid >> 3, lc = (tid & 7) * 4;
    float acc[2][4][4] = {};

    auto issue = [&](int ki) {
        int st = ki % 3, kt = ki * 32;
        float* Xs = dsm + st * 4608;
        float* Ws = dsm + 13824 + st * 2304;
#pragma unroll
        for (int rr = 0; rr < 4; rr++) {
            int r = lr + rr * 32;
            cpa16(&Xs[r * 36 + lc], &X[(size_t)(m0 + r) * NDM + kt + lc]);
        }
#pragma unroll
        for (int rr = 0; rr < 2; rr++) {
            int r = lr + rr * 32;
            cpa16(&Ws[r * 36 + lc], &W[(size_t)(n0 + r) * NDM + kt + lc]);
        }
    };
    issue(0); CP_COMMIT();
    issue(1); CP_COMMIT();
    for (int ki = 0; ki < 16; ki++) {
        if (ki < 15) CP_WAIT1(); else CP_WAIT0();
        __syncthreads();
        if (ki < 14) { issue(ki + 2); CP_COMMIT(); }
        int st = ki % 3;
        const float* Xf = dsm + st * 4608;
        const float* Wf = dsm + 13824 + st * 2304;
#pragma unroll
        for (int ks = 0; ks < 4; ks++) {
            uint32_t a[2][4], bb[4][2];
#pragma unroll
            for (int mi = 0; mi < 2; mi++) {
                int r = wm * 32 + mi * 16 + g;
                a[mi][0] = __float_as_uint(Xf[r*36 + ks*8 + t]);
                a[mi][1] = __float_as_uint(Xf[(r+8)*36 + ks*8 + t]);
                a[mi][2] = __float_as_uint(Xf[r*36 + ks*8 + t + 4]);
                a[mi][3] = __float_as_uint(Xf[(r+8)*36 + ks*8 + t + 4]);
            }
#pragma unroll
            for (int ni = 0; ni < 4; ni++) {
                int c = wn * 32 + ni * 8 + g;
                bb[ni][0] = __float_as_uint(Wf[c*36 + ks*8 + t]);
                bb[ni][1] = __float_as_uint(Wf[c*36 + ks*8 + t + 4]);
            }
#pragma unroll
            for (int mi = 0; mi < 2; mi++)
#pragma unroll
                for (int ni = 0; ni < 4; ni++) mma8(acc[mi][ni], a[mi], bb[ni]);
        }
    }
    // global store of q/k/v, tf32-RN-rounded so consumers skip cvt
#pragma unroll
    for (int mi = 0; mi < 2; mi++)
#pragma unroll
        for (int ni = 0; ni < 4; ni++) {
            int m = m0 + wm*32 + mi*16 + g, n = n0 + wn*32 + ni*8 + 2*t;
            int b = m >> 9, s = m & 511, h = n >> 6, d = n & 63, bh = b*NH + h;
            if (z == 2) {
                g_v[(bh*NDH + d)  *NS + s]     = f2tff(acc[mi][ni][0]);
                g_v[(bh*NDH + d+1)*NS + s]     = f2tff(acc[mi][ni][1]);
                g_v[(bh*NDH + d)  *NS + s + 8] = f2tff(acc[mi][ni][2]);
                g_v[(bh*NDH + d+1)*NS + s + 8] = f2tff(acc[mi][ni][3]);
            } else {
                float* o = (z == 0) ? g_q : g_k;
                float* o1 = &o[((bh*NS + s)    *NDH) + d];
                float* o2 = &o[((bh*NS + s + 8)*NDH) + d];
                o1[0]=f2tff(acc[mi][ni][0]); o1[1]=f2tff(acc[mi][ni][1]);
                o2[0]=f2tff(acc[mi][ni][2]); o2[1]=f2tff(acc[mi][ni][3]);
            }
        }
    if (z != 0) return;

    // ---- fused qr/qb epilogue (this CTA holds q[m0..m0+127][head hB][0..63]) --
    float* Qs  = dsm;             // [128][68]
    float* WrT = dsm + 13824;     // [64 r][68 d]: WrT[r][d] = Wr[d][r]
    float* brs = dsm + 18176;
    const int hB = blockIdx.y;
    __syncthreads();   // everyone done reading stage buffers
#pragma unroll
    for (int mi = 0; mi < 2; mi++)
#pragma unroll
        for (int ni = 0; ni < 4; ni++) {
            int ml = wm*32 + mi*16 + g, nl = wn*32 + ni*8 + 2*t;
            Qs[ml*68 + nl] = acc[mi][ni][0];     Qs[ml*68 + nl + 1] = acc[mi][ni][1];
            Qs[(ml+8)*68 + nl] = acc[mi][ni][2]; Qs[(ml+8)*68 + nl + 1] = acc[mi][ni][3];
        }
    for (int i = tid; i < 4096; i += 256) {
        int d = i >> 6, r = i & 63;
        WrT[r*68 + d] = Wr[i];     // coalesced read
    }
    if (tid < 64) brs[tid] = br[tid];
    __syncthreads();

    float qacc[2][4][4] = {};
#pragma unroll
    for (int ks = 0; ks < 8; ks++) {
        uint32_t a[2][4], bb[4][2];
#pragma unroll
        for (int mi = 0; mi < 2; mi++) {
            int r = wm * 32 + mi * 16 + g;
            a[mi][0] = f2tf(Qs[r*68 + ks*8 + t]);     a[mi][1] = f2tf(Qs[(r+8)*68 + ks*8 + t]);
            a[mi][2] = f2tf(Qs[r*68 + ks*8 + t + 4]); a[mi][3] = f2tf(Qs[(r+8)*68 + ks*8 + t + 4]);
        }
#pragma unroll
        for (int ni = 0; ni < 4; ni++) {
            int c = wn * 32 + ni * 8 + g;
            bb[ni][0] = f2tf(WrT[c*68 + ks*8 + t]); bb[ni][1] = f2tf(WrT[c*68 + ks*8 + t + 4]);
        }
#pragma unroll
        for (int mi = 0; mi < 2; mi++)
#pragma unroll
            for (int ni = 0; ni < 4; ni++) mma8(qacc[mi][ni], a[mi], bb[ni]);
    }
#pragma unroll
    for (int mi = 0; mi < 2; mi++)
#pragma unroll
        for (int ni = 0; ni < 4; ni++) {
            int ml = wm*32 + mi*16 + g, col = wn*32 + ni*8 + 2*t;
            int m = m0 + ml, b = m >> 9, s = m & 511;
            float* o1 = &g_qr[(((size_t)(b*NH + hB)*NS + s)     ) * NDH + col];
            float* o2 = &g_qr[(((size_t)(b*NH + hB)*NS + (s+8)) ) * NDH + col];
            o1[0] = f2tff(qacc[mi][ni][0]) * 0.125f; o1[1] = f2tff(qacc[mi][ni][1]) * 0.125f;
            o2[0] = f2tff(qacc[mi][ni][2]) * 0.125f; o2[1] = f2tff(qacc[mi][ni][3]) * 0.125f;
        }
    // qb: 2 threads per row (128 rows)
    {
        int row = tid >> 1, half = tid & 1;
        float p = 0.f;
#pragma unroll
        for (int d = 0; d < 32; d++) p += Qs[row*68 + half*32 + d] * brs[half*32 + d];
        p += __shfl_xor_sync(0xffffffffu, p, 1);
        if (half == 0) {
            int m = m0 + row, b = m >> 9, s = m & 511;
            g_qb[(b*NH + hB)*NS + s] = p * 0.125f;
        }
    }
}

// ======= K3: 0.125*q k^T per (b,h), scores -> [b][q][h][k]; cvt-free ========
__global__ void __launch_bounds__(256) k_qk() {
    const int bh = blockIdx.z, b = bh >> 3, h = bh & 7;
    const float* __restrict__ Q = &g_q[(size_t)bh * NS * NDH];
    const float* __restrict__ K = &g_k[(size_t)bh * NS * NDH];
    __shared__ float As[64 * 68], Bs[64 * 68];
    const int tid = threadIdx.x, lane = tid & 31, w = tid >> 5;
    const int g = lane >> 2, t = lane & 3, wm = w >> 2, wn = w & 3;
    const int m0 = blockIdx.x * 64, n0 = blockIdx.y * 64;
#pragma unroll
    for (int rr = 0; rr < 4; rr++) {
        int r = (tid >> 4) + rr * 16, c4 = (tid & 15) * 4;
        cpa16(&As[r * 68 + c4], &Q[(m0 + r) * NDH + c4]);
        cpa16(&Bs[r * 68 + c4], &K[(n0 + r) * NDH + c4]);
    }
    CP_COMMIT(); CP_WAIT0();
    __syncthreads();
    float acc[2][2][4] = {};
#pragma unroll
    for (int ks = 0; ks < 8; ks++) {
        uint32_t a[2][4], bb[2][2];
#pragma unroll
        for (int mi = 0; mi < 2; mi++) {
            int r = wm * 32 + mi * 16 + g;
            a[mi][0] = __float_as_uint(As[r*68 + ks*8 + t]);
            a[mi][1] = __float_as_uint(As[(r+8)*68 + ks*8 + t]);
            a[mi][2] = __float_as_uint(As[r*68 + ks*8 + t + 4]);
            a[mi][3] = __float_as_uint(As[(r+8)*68 + ks*8 + t + 4]);
        }
#pragma unroll
        for (int ni = 0; ni < 2; ni++) {
            int c = wn * 16 + ni * 8 + g;
            bb[ni][0] = __float_as_uint(Bs[c*68 + ks*8 + t]);
            bb[ni][1] = __float_as_uint(Bs[c*68 + ks*8 + t + 4]);
        }
#pragma unroll
        for (int mi = 0; mi < 2; mi++)
#pragma unroll
            for (int ni = 0; ni < 2; ni++) mma8(acc[mi][ni], a[mi], bb[ni]);
    }
#pragma unroll
    for (int mi = 0; mi < 2; mi++)
#pragma unroll
        for (int ni = 0; ni < 2; ni++) {
            int m = m0 + wm*32 + mi*16 + g, n = n0 + wn*16 + ni*8 + 2*t;
            float* o1 = &g_s1[((size_t)(b*NS + m)    *NH + h)*NS + n];
            float* o2 = &g_s1[((size_t)(b*NS + m + 8)*NH + h)*NS + n];
            o1[0] = acc[mi][ni][0] * 0.125f; o1[1] = acc[mi][ni][1] * 0.125f;
            o2[0] = acc[mi][ni][2] * 0.125f; o2[1] = acc[mi][ni][3] * 0.125f;
        }
}

// ===== K4: per (b,q): rel mma + scores(reg) + mask + softmax ================
// rel fed to mma as raw bits (tf32 truncation) -> cvt-free chunk loop
// dyn smem floats: relb[2][128*68] | qrs[8*68] | qbs[8] | red[128]
#define RELW   (128 * 68)
#define OFF_QR (2 * RELW)
#define OFF_QB (OFF_QR + 8 * 68)
#define OFF_RED (OFF_QB + 8)
#define K4_SMEM ((OFF_RED + 128) * 4)   // 72,992 bytes -> 3 CTAs/SM

__global__ void __launch_bounds__(256) k_relsm(const float* __restrict__ REL,
                                               const int* __restrict__ GRAPH) {
    extern __shared__ float sm[];
    float* relb = sm;
    uint32_t* qrs = (uint32_t*)(sm + OFF_QR);
    float* qbs = sm + OFF_QB;
    float* red = sm + OFF_RED;   // [2][8 warps][8 h]

    const int q = blockIdx.x, b = blockIdx.y;
    const int tid = threadIdx.x, lane = tid & 31, w = tid >> 5;
    const int g = lane >> 2, t = lane & 3;

    const float* relrow = REL + (size_t)(b*NS + q) * NS * NDH;
    const float* scrow  = &g_s1[(size_t)(b*NS + q) * NH * NS];
    const int*   grow   = &GRAPH[(size_t)(b*NS + q) * NS];

    auto issue_rel = [&](int ch) {
        const float* src = relrow + (size_t)ch * 128 * NDH;
        float* dst = relb + (ch & 1) * RELW;
        int c4 = (tid & 15) * 4, r0 = tid >> 4;
#pragma unroll
        for (int rr = 0; rr < 8; rr++) {
            int r = r0 + rr * 16;
            cpa16(&dst[r * 68 + c4], src + (size_t)r * NDH + c4);
        }
    };
    issue_rel(0); CP_COMMIT();
    issue_rel(1); CP_COMMIT();

    // scores + graph -> registers (masked at load)
    float sc[16];
#pragma unroll
    for (int ch = 0; ch < 4; ch++) {
        int k0 = ch * 128 + w * 16;
#pragma unroll
        for (int j = 0; j < 4; j++) {
            int k = k0 + g + ((j >= 2) ? 8 : 0);
            int h = 2 * t + (j & 1);
            sc[ch*4+j] = scrow[(size_t)h*NS + k] + (1.f - (float)grow[k]) * -1e9f;
        }
    }
    if (tid < 8) qbs[tid] = g_qb[(b*NH + tid)*NS + q];
    for (int i = tid; i < 512; i += 256) {
        int h = i >> 6, r = i & 63;
        qrs[h * 68 + r] = __float_as_uint(g_qr[(size_t)((b*NH + h)*NS + q) * NDH + r]);
    }
    __syncthreads();
    uint32_t bf[8][2];
#pragma unroll
    for (int ks = 0; ks < 8; ks++) {
        bf[ks][0] = qrs[g*68 + ks*8 + t];
        bf[ks][1] = qrs[g*68 + ks*8 + t + 4];
    }
    const float qb0 = qbs[2*t], qb1 = qbs[2*t + 1];

    for (int ch = 0; ch < 4; ch++) {
        if (ch < 3) CP_WAIT1(); else CP_WAIT0();
        __syncthreads();
        const float* buf = relb + (ch & 1) * RELW;
        float c[4] = {0,0,0,0};
        int r0 = w * 16 + g;
#pragma unroll
        for (int ks = 0; ks < 8; ks++) {
            uint32_t a[4];
            a[0] = __float_as_uint(buf[r0*68 + ks*8 + t]);
            a[1] = __float_as_uint(buf[(r0+8)*68 + ks*8 + t]);
            a[2] = __float_as_uint(buf[r0*68 + ks*8 + t + 4]);
            a[3] = __float_as_uint(buf[(r0+8)*68 + ks*8 + t + 4]);
            mma8(c, a, bf[ks]);
        }
#pragma unroll
        for (int j = 0; j < 4; j++)
            sc[ch*4+j] += c[j] + ((j & 1) ? qb1 : qb0);
        __syncthreads();
        if (ch < 2) { issue_rel(ch + 2); CP_COMMIT(); }
    }
    // softmax: even sc index -> h=2t, odd -> h=2t+1
    float mx0 = -3e38f, mx1 = -3e38f;
#pragma unroll
    for (int i = 0; i < 16; i++) { if (i & 1) mx1 = fmaxf(mx1, sc[i]); else mx0 = fmaxf(mx0, sc[i]); }
#pragma unroll
    for (int o = 4; o < 32; o <<= 1) {
        mx0 = fmaxf(mx0, __shfl_xor_sync(0xffffffffu, mx0, o));
        mx1 = fmaxf(mx1, __shfl_xor_sync(0xffffffffu, mx1, o));
    }
    if (g == 0) { red[w*8 + 2*t] = mx0; red[w*8 + 2*t+1] = mx1; }
    __syncthreads();
    float fm0 = -3e38f, fm1 = -3e38f;
#pragma unroll
    for (int ww = 0; ww < 8; ww++) {
        fm0 = fmaxf(fm0, red[ww*8 + 2*t]); fm1 = fmaxf(fm1, red[ww*8 + 2*t+1]);
    }
    float s0 = 0.f, s1 = 0.f;
#pragma unroll
    for (int i = 0; i < 16; i++) {
        float e = __expf(sc[i] - ((i & 1) ? fm1 : fm0));
        sc[i] = e;
        if (i & 1) s1 += e; else s0 += e;
    }
#pragma unroll
    for (int o = 4; o < 32; o <<= 1) {
        s0 += __shfl_xor_sync(0xffffffffu, s0, o);
        s1 += __shfl_xor_sync(0xffffffffu, s1, o);
    }
    if (g == 0) { red[64 + w*8 + 2*t] = s0; red[64 + w*8 + 2*t+1] = s1; }
    __syncthreads();
    float ts0 = 0.f, ts1 = 0.f;
#pragma unroll
    for (int ww = 0; ww < 8; ww++) { ts0 += red[64 + ww*8 + 2*t]; ts1 += red[64 + ww*8 + 2*t+1]; }
    float r0i = 1.f / ts0, r1i = 1.f / ts1;

    // stage probs [h][k] into relb (tf32-RN-rounded so k_pv skips cvt)
    float* pbuf = relb;
    __syncthreads();
#pragma unroll
    for (int ch = 0; ch < 4; ch++) {
        int k0 = ch * 128 + w * 16;
#pragma unroll
        for (int j = 0; j < 4; j++) {
            int k = k0 + g + ((j >= 2) ? 8 : 0);
            int h = 2 * t + (j & 1);
            pbuf[h * NS + k] = f2tff(sc[ch*4+j] * ((j & 1) ? r1i : r0i));
        }
    }
    __syncthreads();
    float* pout = &g_p[(size_t)(b*NS + q) * NH * NS];
    for (int i = tid; i < 1024; i += 256)
        *(float4*)&pout[i * 4] = *(const float4*)&pbuf[i * 4];
}

// ========= K5: out = probs @ v per (b,h), BM=64, 3-stage ring, cvt-free =====
#define K5_SMEM (3 * 2 * 2304 * 4)   // 55,296 bytes

__global__ void __launch_bounds__(256) k_pv(float* __restrict__ OUT) {
    extern __shared__ float dsm[];
    const int bh = blockIdx.z, b = bh >> 3, h = bh & 7;
    const float* __restrict__ VT = &g_v[(size_t)bh * NDH * NS];
    const int tid = threadIdx.x, lane = tid & 31, w = tid >> 5;
    const int g = lane >> 2, t = lane & 3, wm = w >> 2, wn = w & 3;
    const int m0 = blockIdx.x * 64;
    const int lr = tid >> 3, lc = (tid & 7) * 4;
    float acc[2][2][4] = {};

    auto issue = [&](int ki) {
        int st = ki % 3, kt = ki * 32;
        float* As = dsm + st * 2304;
        float* Bs = dsm + 6912 + st * 2304;
#pragma unroll
        for (int rr = 0; rr < 2; rr++) {
            int r = lr + rr * 32;
            cpa16(&As[r * 36 + lc], &g_p[((size_t)(b*NS + m0 + r)*NH + h)*NS + kt + lc]);
            cpa16(&Bs[r * 36 + lc], &VT[(size_t)r * NS + kt + lc]);
        }
    };
    issue(0); CP_COMMIT();
    issue(1); CP_COMMIT();
    for (int ki = 0; ki < 16; ki++) {
        if (ki < 15) CP_WAIT1(); else CP_WAIT0();
        __syncthreads();
        if (ki < 14) { issue(ki + 2); CP_COMMIT(); }
        int st = ki % 3;
        const float* Af = dsm + st * 2304;
        const float* Bf = dsm + 6912 + st * 2304;
#pragma unroll
        for (int ks = 0; ks < 4; ks++) {
            uint32_t a[2][4], bb[2][2];
#pragma unroll
            for (int mi = 0; mi < 2; mi++) {
                int r = wm * 32 + mi * 16 + g;
                a[mi][0] = __float_as_uint(Af[r*36 + ks*8 + t]);
                a[mi][1] = __float_as_uint(Af[(r+8)*36 + ks*8 + t]);
                a[mi][2] = __float_as_uint(Af[r*36 + ks*8 + t + 4]);
                a[mi][3] = __float_as_uint(Af[(r+8)*36 + ks*8 + t + 4]);
            }
#pragma unroll
            for (int ni = 0; ni < 2; ni++) {
                int c = wn * 16 + ni * 8 + g;
                bb[ni][0] = __float_as_uint(Bf[c*36 + ks*8 + t]);
                bb[ni][1] = __float_as_uint(Bf[c*36 + ks*8 + t + 4]);
            }
#pragma unroll
            for (int mi = 0; mi < 2; mi++)
#pragma unroll
                for (int ni = 0; ni < 2; ni++) mma8(acc[mi][ni], a[mi], bb[ni]);
        }
    }
#pragma unroll
    for (int mi = 0; mi < 2; mi++)
#pragma unroll
        for (int ni = 0; ni < 2; ni++) {
            int m = m0 + wm*32 + mi*16 + g, n = wn*16 + ni*8 + 2*t;
            float* o1 = &OUT[(size_t)(b*NS + m)    *NDM + h*NDH + n];
            float* o2 = &OUT[(size_t)(b*NS + m + 8)*NDM + h*NDH + n];
            o1[0]=acc[mi][ni][0]; o1[1]=acc[mi][ni][1];
            o2[0]=acc[mi][ni][2]; o2[1]=acc[mi][ni][3];
        }
}

extern "C" void kernel_launch(void* const* d_in, const int* in_sizes, int n_in,
                              void* d_out, int out_size) {
    const float* X     = (const float*)d_in[0];
    const int*   GRAPH = (const int*)  d_in[1];
    const float* REL   = (const float*)d_in[2];
    const float* Wq    = (const float*)d_in[3];
    const float* Wk    = (const float*)d_in[4];
    const float* Wv    = (const float*)d_in[5];
    const float* Wr    = (const float*)d_in[6];
    const float* br    = (const float*)d_in[7];
    float* OUT = (float*)d_out;

    static bool attr_set = false;
    if (!attr_set) {
        cudaFuncSetAttribute(k_qkv,   cudaFuncAttributeMaxDynamicSharedMemorySize, K1_SMEM);
        cudaFuncSetAttribute(k_relsm, cudaFuncAttributeMaxDynamicSharedMemorySize, K4_SMEM);
        cudaFuncSetAttribute(k_pv,    cudaFuncAttributeMaxDynamicSharedMemorySize, K5_SMEM);
        attr_set = true;
    }

    k_qkv  <<<dim3(16, 8, 3), 256, K1_SMEM>>>(X, Wq, Wk, Wv, Wr, br);
    k_qk   <<<dim3(8, 8, 32), 256>>>();
    k_relsm<<<dim3(512, 4), 256, K4_SMEM>>>(REL, GRAPH);
    k_pv   <<<dim3(8, 1, 32), 256, K5_SMEM>>>(OUT);
}